// round 11
// baseline (speedup 1.0000x reference)
#include <cuda_runtime.h>
#include <cuda_bf16.h>
#include <cstdint>
#include <cstddef>
#include <math.h>

// ---------------------------------------------------------------------------
// HoloKVAttention, all GEMMs bf16x3 split precision on tensor cores.
// R11: 64x64 warp tiles (4-warp CTAs) for big GEMMs, 2-stage cp.async,
// fixup->split fusion and batched LoRA stage-2 kept from R10.
// ---------------------------------------------------------------------------

#define HID   1024
#define NH    16
#define HD    64
#define KF    4
#define LR    64
#define BATCH 2
#define SEQ   2048
#define NTOK  (BATCH*SEQ)   // 4096
#define NS    (SEQ/KF)      // 512
#define NBH   (BATCH*NH)    // 32

// ------------------------- device scratch (static) -------------------------
__device__ float g_QKV[(size_t)NTOK*3*HID];   // [tok][Q|K|V]
__device__ float g_XA[NTOK*128];              // LoRA stage-1 out
__device__ float g_Ks[NBH*SEQ*HD];
__device__ float g_Vs[NBH*SEQ*HD];
__device__ float g_fullV[NBH*NS*HD];
__device__ float g_scores[(size_t)NBH*SEQ*NS];
__device__ float g_wcurr[NBH*SEQ];
__device__ float g_Ohead[NBH*SEQ*HD];
__device__ float2 g_cs_tab[SEQ*32];

// bf16 split operand buffers
__device__ __align__(16) __nv_bfloat16 g_Xs[(size_t)NTOK*3*HID];     // [Xh|Xh|Xl] (reused for O)
__device__ __align__(16) __nv_bfloat16 g_Wqkv[(size_t)3*HID*3*HID];  // combined hlh, ld=3072
__device__ __align__(16) __nv_bfloat16 g_Wsplit[3*HID*HID];          // Wo hlh
__device__ __align__(16) __nv_bfloat16 g_AB[3*HID*128];              // [Aq|Av] or Ao hlh
__device__ __align__(16) __nv_bfloat16 g_Bsplit[2*3*LR*HID];         // stacked Bq,Bv (or Bo)
__device__ __align__(16) __nv_bfloat16 g_XAsplit[NTOK*2*3*LR];       // hhl x2, ld=384
__device__ __align__(16) __nv_bfloat16 g_Qas[(size_t)NBH*SEQ*3*HD];  // ld=192
__device__ __align__(16) __nv_bfloat16 g_KTs[(size_t)NBH*3*HD*NS];   // ld=NS
__device__ __align__(16) __nv_bfloat16 g_FVs[(size_t)NBH*3*NS*HD];   // interleaved, ld=HD
__device__ __align__(16) __nv_bfloat16 g_Ws[(size_t)NBH*SEQ*3*NS];   // ld=1536

__device__ __forceinline__ float hsign(int step, int col) {
    return ((0x6CA0 >> ((step << 2) | (col & 3))) & 1) ? -1.0f : 1.0f;
}

__device__ __forceinline__ void cp_async16(void* smem, const void* gmem) {
    uint32_t s = (uint32_t)__cvta_generic_to_shared(smem);
    asm volatile("cp.async.cg.shared.global [%0], [%1], 16;" :: "r"(s), "l"(gmem));
}

// --------------------------- bf16 split kernels ----------------------------
__global__ void split_hhl(const float* __restrict__ src,
                          __nv_bfloat16* __restrict__ dst, int M, int K) {
    int idx = blockIdx.x * blockDim.x + threadIdx.x;
    if (idx >= M * K) return;
    int m = idx / K, k = idx - m * K;
    float x = src[idx];
    __nv_bfloat16 h = __float2bfloat16(x);
    __nv_bfloat16 l = __float2bfloat16(x - __bfloat162float(h));
    long long base = (long long)m * (3 * K);
    dst[base + k] = h; dst[base + K + k] = h; dst[base + 2*K + k] = l;
}
__global__ void split_hlh_off(const float* __restrict__ src,
                              __nv_bfloat16* __restrict__ dst,
                              int K, int N, int ldDst, int colOff) {
    int idx = blockIdx.x * blockDim.x + threadIdx.x;
    if (idx >= K * N) return;
    int k = idx / N, n = idx - k * N;
    float x = src[idx];
    __nv_bfloat16 h = __float2bfloat16(x);
    __nv_bfloat16 l = __float2bfloat16(x - __bfloat162float(h));
    long long col = colOff + n;
    dst[(long long)k * ldDst + col]          = h;
    dst[(long long)(K + k) * ldDst + col]    = l;
    dst[(long long)(2*K + k) * ldDst + col]  = h;
}
// XA [4096x128] -> XAs [4096x384]: cols 0-63 hhl at 0/64/128, 64-127 at 192/256/320
__global__ void split_hhl2(const float* __restrict__ src,
                           __nv_bfloat16* __restrict__ dst) {
    int idx = blockIdx.x * blockDim.x + threadIdx.x;
    if (idx >= NTOK * 128) return;
    int m = idx >> 7, c = idx & 127;
    int grp = c >> 6, k = c & 63;
    float x = src[idx];
    __nv_bfloat16 h = __float2bfloat16(x);
    __nv_bfloat16 l = __float2bfloat16(x - __bfloat162float(h));
    long long base = (long long)m * 384 + grp * 192;
    dst[base + k] = h; dst[base + 64 + k] = h; dst[base + 128 + k] = l;
}

// ---------- multi-stage cp.async bf16 tensor-core GEMM ---------------------
// C[M,N] fp32 = A[M,K] @ B[K,N], leading dims ldA/ldB/ldC, batched over z.
// causal: 0 none; 1 scores tile-skip; 2 PV interleaved K-limit.
template<int BM, int BN, int BK, int WM, int WN, int STAGES>
__global__ __launch_bounds__(WM*WN*32)
void mma_gemm(const __nv_bfloat16* __restrict__ A,
              const __nv_bfloat16* __restrict__ B,
              float* __restrict__ C, int M, int N, int K,
              int ldA, int ldB, int ldC,
              long long sA, long long sB, long long sC,
              int accumulate, int causal)
{
    constexpr int NTH = WM * WN * 32;
    constexpr int WTM = BM / WM, WTN = BN / WN;
    constexpr int MT = WTM / 16, NTt = WTN / 8;
    constexpr int AP = BK + 8, BP = BN + 8;
    extern __shared__ __align__(16) __nv_bfloat16 smem[];
    __nv_bfloat16* AsBase = smem;                         // STAGES * BM * AP
    __nv_bfloat16* BsBase = smem + STAGES * BM * AP;      // STAGES * BK * BP

    const int m0 = blockIdx.y * BM, n0 = blockIdx.x * BN;
    if (causal == 1 && n0 > ((m0 + BM - 1) >> 2)) return;
    int kend = K;
    if (causal == 2) {
        int kl = 3 * (((m0 + BM - 1) >> 2) + 1);
        kl = (kl + BK - 1) / BK * BK;
        if (kl < kend) kend = kl;
    }
    const int KT = kend / BK;

    const long long z = blockIdx.z;
    A += z * sA; B += z * sB; C += z * sC;

    const int tid = threadIdx.x, lane = tid & 31;
    const int wid = tid >> 5;
    const int wm = wid / WN, wn = wid % WN;

    float acc[MT][NTt][4] = {};

    auto load_stage = [&](int kt, int st) {
        const int k0 = kt * BK;
        __nv_bfloat16* As = AsBase + st * BM * AP;
        __nv_bfloat16* Bs = BsBase + st * BK * BP;
        #pragma unroll
        for (int i = tid; i < BM * BK / 8; i += NTH) {
            int r = i / (BK / 8), c = (i % (BK / 8)) * 8;
            cp_async16(As + r * AP + c, &A[(long long)(m0 + r) * ldA + k0 + c]);
        }
        #pragma unroll
        for (int i = tid; i < BK * BN / 8; i += NTH) {
            int r = i / (BN / 8), c = (i % (BN / 8)) * 8;
            cp_async16(Bs + r * BP + c, &B[(long long)(k0 + r) * ldB + n0 + c]);
        }
        asm volatile("cp.async.commit_group;");
    };

    #pragma unroll
    for (int s = 0; s < STAGES - 1; s++)
        if (s < KT) load_stage(s, s);

    for (int kt = 0; kt < KT; kt++) {
        const int st = kt % STAGES;
        if (kt + STAGES - 1 < KT) {
            load_stage(kt + STAGES - 1, (kt + STAGES - 1) % STAGES);
            asm volatile("cp.async.wait_group %0;" :: "n"(STAGES - 1));
        } else {
            asm volatile("cp.async.wait_group 0;");
        }
        __syncthreads();
        __nv_bfloat16* As = AsBase + st * BM * AP;
        __nv_bfloat16* Bs = BsBase + st * BK * BP;

        #pragma unroll
        for (int ks = 0; ks < BK / 16; ks++) {
            uint32_t a[MT][4], b[NTt][2];
            #pragma unroll
            for (int mt = 0; mt < MT; mt++) {
                uint32_t s = (uint32_t)__cvta_generic_to_shared(
                    As + (wm*WTM + mt*16 + (lane & 15)) * AP + ks*16 + ((lane >> 4) << 3));
                asm volatile("ldmatrix.sync.aligned.m8n8.x4.shared.b16 {%0,%1,%2,%3}, [%4];"
                    : "=r"(a[mt][0]), "=r"(a[mt][1]), "=r"(a[mt][2]), "=r"(a[mt][3])
                    : "r"(s));
            }
            #pragma unroll
            for (int np = 0; np < NTt / 2; np++) {
                uint32_t s = (uint32_t)__cvta_generic_to_shared(
                    Bs + (ks*16 + (lane & 15)) * BP + wn*WTN + np*16 + ((lane >> 4) << 3));
                asm volatile("ldmatrix.sync.aligned.m8n8.x4.trans.shared.b16 {%0,%1,%2,%3}, [%4];"
                    : "=r"(b[np*2][0]), "=r"(b[np*2][1]),
                      "=r"(b[np*2+1][0]), "=r"(b[np*2+1][1])
                    : "r"(s));
            }
            #pragma unroll
            for (int mt = 0; mt < MT; mt++)
                #pragma unroll
                for (int nt = 0; nt < NTt; nt++)
                    asm volatile(
                        "mma.sync.aligned.m16n8k16.row.col.f32.bf16.bf16.f32 "
                        "{%0,%1,%2,%3}, {%4,%5,%6,%7}, {%8,%9}, {%0,%1,%2,%3};"
                        : "+f"(acc[mt][nt][0]), "+f"(acc[mt][nt][1]),
                          "+f"(acc[mt][nt][2]), "+f"(acc[mt][nt][3])
                        : "r"(a[mt][0]), "r"(a[mt][1]), "r"(a[mt][2]), "r"(a[mt][3]),
                          "r"(b[nt][0]), "r"(b[nt][1]));
        }
        __syncthreads();
    }

    #pragma unroll
    for (int mt = 0; mt < MT; mt++) {
        int row = m0 + wm*WTM + mt*16 + (lane >> 2);
        #pragma unroll
        for (int nt = 0; nt < NTt; nt++) {
            int col = n0 + wn*WTN + nt*8 + ((lane & 3) << 1);
            float2* p0 = (float2*)&C[(long long)row * ldC + col];
            float2* p1 = (float2*)&C[(long long)(row + 8) * ldC + col];
            float2 v0 = make_float2(acc[mt][nt][0], acc[mt][nt][1]);
            float2 v1 = make_float2(acc[mt][nt][2], acc[mt][nt][3]);
            if (accumulate) {
                float2 o0 = *p0, o1 = *p1;
                v0.x += o0.x; v0.y += o0.y; v1.x += o1.x; v1.y += o1.y;
            }
            *p0 = v0; *p1 = v1;
        }
    }
}

// ----------------------------- rope cos/sin table --------------------------
__global__ void rope_table_kernel() {
    int s = blockIdx.x;
    int i = threadIdx.x;
    double invf = exp(-(double)i * (log(10000.0) / 32.0));
    double ang  = (double)s * invf;
    g_cs_tab[s*32 + i] = make_float2((float)cos(ang), (float)sin(ang));
}

// ------ RoPE + Hadamard phase; reads combined QKV; emits Qa split ----------
__global__ void rope_phase_kernel() {
    long long idx = (long long)blockIdx.x * blockDim.x + threadIdx.x;
    if (idx >= (long long)NTOK * HID) return;
    int d = (int)(idx & 63);
    int h = (int)((idx >> 6) & 15);
    int t = (int)(idx >> 10);
    int b = t >> 11;
    int s = t & (SEQ - 1);
    int step = s & 3;
    float sgn = hsign(step, d);

    long long qoff = (long long)t * 3072 + h * 64 + d;
    long long qpo  = (d < 32) ? qoff + 32 : qoff - 32;
    int i = d & 31;
    float2 cs = g_cs_tab[s*32 + i];

    float qv = g_QKV[qoff],        qp = g_QKV[qpo];
    float kv = g_QKV[qoff + 1024], kp = g_QKV[qpo + 1024];
    float vv = g_QKV[qoff + 2048];
    float qr = (d < 32) ? (qv*cs.x - qp*cs.y) : (qv*cs.x + qp*cs.y);
    float kr = (d < 32) ? (kv*cs.x - kp*cs.y) : (kv*cs.x + kp*cs.y);

    int bh = b*NH + h;
    long long hoff = (long long)(bh*SEQ + s) * HD + d;
    float qa = qr * sgn * 0.125f;
    g_Ks[hoff] = kr * sgn * 0.5f;
    g_Vs[hoff] = vv * sgn * 0.5f;

    __nv_bfloat16 qh = __float2bfloat16(qa);
    __nv_bfloat16 ql = __float2bfloat16(qa - __bfloat162float(qh));
    long long qbase = (long long)(bh*SEQ + s) * (3*HD) + d;
    g_Qas[qbase]        = qh;
    g_Qas[qbase + HD]   = qh;
    g_Qas[qbase + 2*HD] = ql;
}

// ---- full_K / full_V per slot; emits split B-operands for both GEMMs ------
__global__ void reduce_full_kernel() {
    int idx = blockIdx.x * blockDim.x + threadIdx.x;
    if (idx >= NBH*NS*HD) return;
    int d    = idx & 63;
    int slot = (idx >> 6) & (NS - 1);
    int bh   = idx >> 15;
    long long base = (long long)(bh*SEQ + slot*KF) * HD + d;
    float sk = 0.f, sv = 0.f;
    #pragma unroll
    for (int j = 0; j < KF; j++) { sk += g_Ks[base + j*HD]; sv += g_Vs[base + j*HD]; }
    g_fullV[idx] = sv;

    __nv_bfloat16 kh = __float2bfloat16(sk);
    __nv_bfloat16 kl = __float2bfloat16(sk - __bfloat162float(kh));
    long long ktb = ((long long)bh * (3*HD) + d) * NS + slot;
    g_KTs[ktb]                        = kh;
    g_KTs[ktb + (long long)HD * NS]   = kl;
    g_KTs[ktb + (long long)2*HD * NS] = kh;

    __nv_bfloat16 vh = __float2bfloat16(sv);
    __nv_bfloat16 vl = __float2bfloat16(sv - __bfloat162float(vh));
    long long fvb = ((long long)bh * (3*NS) + 3*slot) * HD + d;
    g_FVs[fvb]        = vh;
    g_FVs[fvb + HD]   = vl;
    g_FVs[fvb + 2*HD] = vh;
}

// --------- softmax per query (one warp); W split up to tile limit ----------
__global__ void softmax_kernel() {
    int warp = (blockIdx.x * blockDim.x + threadIdx.x) >> 5;
    int lane = threadIdx.x & 31;
    if (warp >= NBH*SEQ) return;
    int bh = warp / SEQ;
    int q  = warp - bh*SEQ;
    int slot = q >> 2, step = q & 3;

    const __nv_bfloat16* qrow = g_Qas + (long long)warp * (3*HD);
    float qa0 = __bfloat162float(qrow[lane])      + __bfloat162float(qrow[2*HD + lane]);
    float qa1 = __bfloat162float(qrow[32 + lane]) + __bfloat162float(qrow[2*HD + 32 + lane]);

    long long krow = (long long)(bh*SEQ + slot*KF) * HD;
    float pk0 = 0.f, pk1 = 0.f;
    for (int j = 0; j <= step; j++) {
        pk0 += g_Ks[krow + j*HD + lane];
        pk1 += g_Ks[krow + j*HD + lane + 32];
    }
    float cs = qa0*pk0 + qa1*pk1;
    #pragma unroll
    for (int o = 16; o; o >>= 1) cs += __shfl_xor_sync(0xFFFFFFFFu, cs, o);

    float* row = g_scores + (long long)bh*SEQ*NS + (long long)q*NS;

    float m = cs;
    for (int s = lane; s < slot; s += 32) m = fmaxf(m, row[s]);
    #pragma unroll
    for (int o = 16; o; o >>= 1) m = fmaxf(m, __shfl_xor_sync(0xFFFFFFFFu, m, o));

    float e_cs = expf(cs - m);
    float lsum = 0.f;
    for (int s = lane; s < slot; s += 32) {
        float e = expf(row[s] - m);
        row[s] = e;
        lsum += e;
    }
    #pragma unroll
    for (int o = 16; o; o >>= 1) lsum += __shfl_xor_sync(0xFFFFFFFFu, lsum, o);
    float inv = 1.0f / (lsum + e_cs);

    int smax_tile = (q | 127) >> 2;   // PV BK=32: 3*(smax+1) divisible, exact
    __nv_bfloat16* wrow = g_Ws + (long long)warp * (3*NS);
    for (int s = lane; s <= smax_tile; s += 32) {
        float w;
        if (s < slot)       w = row[s] * inv;
        else if (s == slot) w = e_cs * inv;
        else                w = 0.0f;
        __nv_bfloat16 h = __float2bfloat16(w);
        __nv_bfloat16 l = __float2bfloat16(w - __bfloat162float(h));
        wrow[3*s]     = h;
        wrow[3*s + 1] = h;
        wrow[3*s + 2] = l;
    }
    if (lane == 0) g_wcurr[warp] = e_cs * inv;
}

// --- fixup + output phase; writes O activations directly as hhl split ------
__global__ void fixup_kernel() {
    int bhq = blockIdx.x;
    int d = threadIdx.x;
    int bh = bhq >> 11;
    int q  = bhq & (SEQ - 1);
    int slot = q >> 2, step = q & 3;

    float out = g_Ohead[(long long)bhq * HD + d];
    long long vrow = (long long)(bh*SEQ + slot*KF) * HD + d;
    float pv = 0.f;
    for (int j = 0; j <= step; j++) pv += g_Vs[vrow + j*HD];
    float fv = g_fullV[((long long)bh*NS + slot) * HD + d];
    float wc = g_wcurr[bhq];
    float val = (out + wc * (pv - fv)) * hsign(step, d) * 2.0f;

    int b = bh >> 4, h = bh & 15;
    int t = b*SEQ + q;
    int c = h*HD + d;
    __nv_bfloat16 vh = __float2bfloat16(val);
    __nv_bfloat16 vl = __float2bfloat16(val - __bfloat162float(vh));
    long long base = (long long)t * 3072;
    g_Xs[base + c]        = vh;
    g_Xs[base + 1024 + c] = vh;
    g_Xs[base + 2048 + c] = vl;
}

// --------------------------------- launcher --------------------------------
extern "C" void kernel_launch(void* const* d_in, const int* in_sizes, int n_in,
                              void* d_out, int out_size)
{
    (void)in_sizes; (void)n_in; (void)out_size;
    const float* X  = (const float*)d_in[0];
    const float* Wq = (const float*)d_in[1];
    const float* Wk = (const float*)d_in[2];
    const float* Wv = (const float*)d_in[3];
    const float* Wo = (const float*)d_in[4];
    const float* Aq = (const float*)d_in[5];
    const float* Bq = (const float*)d_in[6];
    const float* Av = (const float*)d_in[7];
    const float* Bv = (const float*)d_in[8];
    const float* Ao = (const float*)d_in[9];
    const float* Bo = (const float*)d_in[10];
    float* Y = (float*)d_out;

    float *pQKV, *pXA, *pFV, *pSc, *pOh;
    __nv_bfloat16 *pXs, *pWqkv, *pWs, *pAB, *pBs, *pXAs, *pQas, *pKTs, *pFVs, *pWw;
    cudaGetSymbolAddress((void**)&pQKV, g_QKV);
    cudaGetSymbolAddress((void**)&pXA,  g_XA);
    cudaGetSymbolAddress((void**)&pFV,  g_fullV);
    cudaGetSymbolAddress((void**)&pSc,  g_scores);
    cudaGetSymbolAddress((void**)&pOh,  g_Ohead);
    cudaGetSymbolAddress((void**)&pXs,  g_Xs);
    cudaGetSymbolAddress((void**)&pWqkv, g_Wqkv);
    cudaGetSymbolAddress((void**)&pWs,  g_Wsplit);
    cudaGetSymbolAddress((void**)&pAB,  g_AB);
    cudaGetSymbolAddress((void**)&pBs,  g_Bsplit);
    cudaGetSymbolAddress((void**)&pXAs, g_XAsplit);
    cudaGetSymbolAddress((void**)&pQas, g_Qas);
    cudaGetSymbolAddress((void**)&pKTs, g_KTs);
    cudaGetSymbolAddress((void**)&pFVs, g_FVs);
    cudaGetSymbolAddress((void**)&pWw,  g_Ws);

    // dynamic smem (2 stages)
    const int SM_BIG = 2*(128*(64+8) + 64*(128+8))*2;   // 71680 B <128,128,64,2,2,2>
    const int SM_PV  = 2*(128*(32+8) + 32*(64+8))*2;    // 37888 B <128,64,32,4,2,2>
    cudaFuncSetAttribute(mma_gemm<128,128,64,2,2,2>,
                         cudaFuncAttributeMaxDynamicSharedMemorySize, SM_BIG);
    cudaFuncSetAttribute(mma_gemm<128,64,32,4,2,2>,
                         cudaFuncAttributeMaxDynamicSharedMemorySize, SM_PV);

    const int SPLIT_T = 256;
    #define GRID1D(n) (((n) + SPLIT_T - 1) / SPLIT_T)

    // ---- split X; assemble combined QKV weights + LoRA operands ----
    split_hhl<<<GRID1D(NTOK*HID), SPLIT_T>>>(X, pXs, NTOK, HID);
    split_hlh_off<<<GRID1D(HID*HID), SPLIT_T>>>(Wq, pWqkv, HID, HID, 3*HID, 0);
    split_hlh_off<<<GRID1D(HID*HID), SPLIT_T>>>(Wk, pWqkv, HID, HID, 3*HID, HID);
    split_hlh_off<<<GRID1D(HID*HID), SPLIT_T>>>(Wv, pWqkv, HID, HID, 3*HID, 2*HID);
    split_hlh_off<<<GRID1D(HID*LR), SPLIT_T>>>(Aq, pAB, HID, LR, 128, 0);
    split_hlh_off<<<GRID1D(HID*LR), SPLIT_T>>>(Av, pAB, HID, LR, 128, LR);
    split_hlh_off<<<GRID1D(LR*HID), SPLIT_T>>>(Bq, pBs, LR, HID, HID, 0);
    split_hlh_off<<<GRID1D(LR*HID), SPLIT_T>>>(Bv, pBs + (size_t)3*LR*HID, LR, HID, HID, 0);

    // ---- combined QKV projection ----
    {
        dim3 grid(3*HID/128, NTOK/128);   // 24 x 32
        mma_gemm<128,128,64,2,2,2><<<grid, 128, SM_BIG>>>(
            pXs, pWqkv, pQKV, NTOK, 3*HID, 3*HID, 3*HID, 3*HID, 3*HID,
            0,0,0, 0, 0);
    }
    // ---- LoRA stage-1 (q|v combined, N=128) ----
    {
        dim3 grid(1, NTOK/128);
        mma_gemm<128,128,64,2,2,2><<<grid, 128, SM_BIG>>>(
            pXs, pAB, pXA, NTOK, 128, 3*HID, 3*HID, 128, 128,
            0,0,0, 0, 0);
    }
    split_hhl2<<<GRID1D(NTOK*128), SPLIT_T>>>(pXA, pXAs);
    // ---- LoRA stage-2, batched z=2 (Q cols / V cols) ----
    {
        dim3 grid(HID/128, NTOK/128, 2);
        mma_gemm<128,128,64,2,2,2><<<grid, 128, SM_BIG>>>(
            pXAs, pBs, pQKV, NTOK, HID, 3*LR, 384, HID, 3*HID,
            192, (long long)3*LR*HID, 2048, 1, 0);
    }

    // ---- RoPE + phase (emits Qa split), slot reduction ----
    rope_table_kernel<<<SEQ, 32>>>();
    rope_phase_kernel<<<GRID1D(NTOK*HID), SPLIT_T>>>();
    reduce_full_kernel<<<GRID1D(NBH*NS*HD), SPLIT_T>>>();

    // ---- scores = Qa @ fullKT (batched, causal tile-skip) ----
    {
        dim3 grid(NS/128, SEQ/128, NBH);
        mma_gemm<128,128,64,2,2,2><<<grid, 128, SM_BIG>>>(
            pQas, pKTs, pSc, SEQ, NS, 3*HD, 3*HD, NS, NS,
            (long long)SEQ*3*HD, (long long)3*HD*NS, (long long)SEQ*NS,
            0, /*causal=*/1);
    }
    softmax_kernel<<<(NBH*SEQ*32)/256, 256>>>();

    // ---- Ohead = W @ fullV (batched, interleaved causal K-limit) ----
    {
        dim3 grid(1, SEQ/128, NBH);
        mma_gemm<128,64,32,4,2,2><<<grid, 256, SM_PV>>>(
            pWw, pFVs, pOh, SEQ, HD, 3*NS, 3*NS, HD, HD,
            (long long)SEQ*3*NS, (long long)3*NS*HD, (long long)SEQ*HD,
            0, /*causal=*/2);
    }
    // ---- fixup writes O activations directly in hhl split into g_Xs ----
    fixup_kernel<<<NBH*SEQ, HD>>>();

    // ---- O projection + LoRA ----
    split_hlh_off<<<GRID1D(HID*HID), SPLIT_T>>>(Wo, pWs, HID, HID, HID, 0);
    {
        dim3 grid(HID/128, NTOK/128);
        mma_gemm<128,128,64,2,2,2><<<grid, 128, SM_BIG>>>(
            pXs, pWs, Y, NTOK, HID, 3*HID, 3*HID, HID, HID,
            0,0,0, 0, 0);
    }
    split_hlh_off<<<GRID1D(HID*LR), SPLIT_T>>>(Ao, pAB, HID, LR, LR, 0);
    {
        dim3 grid(1, NTOK/128);   // N=64
        mma_gemm<128,64,32,4,2,2><<<grid, 256, SM_PV>>>(
            pXs, pAB, pXA, NTOK, LR, 3*HID, 3*HID, LR, LR,
            0,0,0, 0, 0);
    }
    split_hhl<<<GRID1D(NTOK*LR), SPLIT_T>>>(pXA, pXAs, NTOK, LR);
    split_hlh_off<<<GRID1D(LR*HID), SPLIT_T>>>(Bo, pBs, LR, HID, HID, 0);
    {
        dim3 grid(HID/128, NTOK/128);
        mma_gemm<128,128,64,2,2,2><<<grid, 128, SM_BIG>>>(
            pXAs, pBs, Y, NTOK, HID, 3*LR, 3*LR, HID, HID,
            0,0,0, 1, 0);
    }
    #undef GRID1D
}

// round 12
// speedup vs baseline: 1.1117x; 1.1117x over previous
#include <cuda_runtime.h>
#include <cuda_bf16.h>
#include <cstdint>
#include <cstddef>
#include <math.h>

// ---------------------------------------------------------------------------
// HoloKVAttention, all GEMMs bf16x3 split precision on tensor cores.
// R12: revert GEMM configs to R9's proven <128,128,64,2,4>/256thr 2-stage;
// keep R10 fusions (fixup->split, batched LoRA stage-2).
// ---------------------------------------------------------------------------

#define HID   1024
#define NH    16
#define HD    64
#define KF    4
#define LR    64
#define BATCH 2
#define SEQ   2048
#define NTOK  (BATCH*SEQ)   // 4096
#define NS    (SEQ/KF)      // 512
#define NBH   (BATCH*NH)    // 32

// ------------------------- device scratch (static) -------------------------
__device__ float g_QKV[(size_t)NTOK*3*HID];   // [tok][Q|K|V]
__device__ float g_XA[NTOK*128];              // LoRA stage-1 out
__device__ float g_Ks[NBH*SEQ*HD];
__device__ float g_Vs[NBH*SEQ*HD];
__device__ float g_fullV[NBH*NS*HD];
__device__ float g_scores[(size_t)NBH*SEQ*NS];
__device__ float g_wcurr[NBH*SEQ];
__device__ float g_Ohead[NBH*SEQ*HD];
__device__ float2 g_cs_tab[SEQ*32];

// bf16 split operand buffers
__device__ __align__(16) __nv_bfloat16 g_Xs[(size_t)NTOK*3*HID];     // [Xh|Xh|Xl] (reused for O)
__device__ __align__(16) __nv_bfloat16 g_Wqkv[(size_t)3*HID*3*HID];  // combined hlh, ld=3072
__device__ __align__(16) __nv_bfloat16 g_Wsplit[3*HID*HID];          // Wo hlh
__device__ __align__(16) __nv_bfloat16 g_AB[3*HID*128];              // [Aq|Av] or Ao hlh
__device__ __align__(16) __nv_bfloat16 g_Bsplit[2*3*LR*HID];         // stacked Bq,Bv (or Bo)
__device__ __align__(16) __nv_bfloat16 g_XAsplit[NTOK*2*3*LR];       // hhl x2, ld=384
__device__ __align__(16) __nv_bfloat16 g_Qas[(size_t)NBH*SEQ*3*HD];  // ld=192
__device__ __align__(16) __nv_bfloat16 g_KTs[(size_t)NBH*3*HD*NS];   // ld=NS
__device__ __align__(16) __nv_bfloat16 g_FVs[(size_t)NBH*3*NS*HD];   // interleaved, ld=HD
__device__ __align__(16) __nv_bfloat16 g_Ws[(size_t)NBH*SEQ*3*NS];   // ld=1536

__device__ __forceinline__ float hsign(int step, int col) {
    return ((0x6CA0 >> ((step << 2) | (col & 3))) & 1) ? -1.0f : 1.0f;
}

__device__ __forceinline__ void cp_async16(void* smem, const void* gmem) {
    uint32_t s = (uint32_t)__cvta_generic_to_shared(smem);
    asm volatile("cp.async.cg.shared.global [%0], [%1], 16;" :: "r"(s), "l"(gmem));
}

// --------------------------- bf16 split kernels ----------------------------
__global__ void split_hhl(const float* __restrict__ src,
                          __nv_bfloat16* __restrict__ dst, int M, int K) {
    int idx = blockIdx.x * blockDim.x + threadIdx.x;
    if (idx >= M * K) return;
    int m = idx / K, k = idx - m * K;
    float x = src[idx];
    __nv_bfloat16 h = __float2bfloat16(x);
    __nv_bfloat16 l = __float2bfloat16(x - __bfloat162float(h));
    long long base = (long long)m * (3 * K);
    dst[base + k] = h; dst[base + K + k] = h; dst[base + 2*K + k] = l;
}
__global__ void split_hlh_off(const float* __restrict__ src,
                              __nv_bfloat16* __restrict__ dst,
                              int K, int N, int ldDst, int colOff) {
    int idx = blockIdx.x * blockDim.x + threadIdx.x;
    if (idx >= K * N) return;
    int k = idx / N, n = idx - k * N;
    float x = src[idx];
    __nv_bfloat16 h = __float2bfloat16(x);
    __nv_bfloat16 l = __float2bfloat16(x - __bfloat162float(h));
    long long col = colOff + n;
    dst[(long long)k * ldDst + col]          = h;
    dst[(long long)(K + k) * ldDst + col]    = l;
    dst[(long long)(2*K + k) * ldDst + col]  = h;
}
// XA [4096x128] -> XAs [4096x384]: cols 0-63 hhl at 0/64/128, 64-127 at 192/256/320
__global__ void split_hhl2(const float* __restrict__ src,
                           __nv_bfloat16* __restrict__ dst) {
    int idx = blockIdx.x * blockDim.x + threadIdx.x;
    if (idx >= NTOK * 128) return;
    int m = idx >> 7, c = idx & 127;
    int grp = c >> 6, k = c & 63;
    float x = src[idx];
    __nv_bfloat16 h = __float2bfloat16(x);
    __nv_bfloat16 l = __float2bfloat16(x - __bfloat162float(h));
    long long base = (long long)m * 384 + grp * 192;
    dst[base + k] = h; dst[base + 64 + k] = h; dst[base + 128 + k] = l;
}

// ---------- 2-stage cp.async bf16 tensor-core GEMM -------------------------
// C[M,N] fp32 = A[M,K] @ B[K,N], leading dims ldA/ldB/ldC, batched over z.
// causal: 0 none; 1 scores tile-skip; 2 PV interleaved K-limit.
template<int BM, int BN, int BK, int WM, int WN, int STAGES>
__global__ __launch_bounds__(WM*WN*32)
void mma_gemm(const __nv_bfloat16* __restrict__ A,
              const __nv_bfloat16* __restrict__ B,
              float* __restrict__ C, int M, int N, int K,
              int ldA, int ldB, int ldC,
              long long sA, long long sB, long long sC,
              int accumulate, int causal)
{
    constexpr int NTH = WM * WN * 32;
    constexpr int WTM = BM / WM, WTN = BN / WN;
    constexpr int MT = WTM / 16, NTt = WTN / 8;
    constexpr int AP = BK + 8, BP = BN + 8;
    extern __shared__ __align__(16) __nv_bfloat16 smem[];
    __nv_bfloat16* AsBase = smem;                         // STAGES * BM * AP
    __nv_bfloat16* BsBase = smem + STAGES * BM * AP;      // STAGES * BK * BP

    const int m0 = blockIdx.y * BM, n0 = blockIdx.x * BN;
    if (causal == 1 && n0 > ((m0 + BM - 1) >> 2)) return;
    int kend = K;
    if (causal == 2) {
        int kl = 3 * (((m0 + BM - 1) >> 2) + 1);
        kl = (kl + BK - 1) / BK * BK;
        if (kl < kend) kend = kl;
    }
    const int KT = kend / BK;

    const long long z = blockIdx.z;
    A += z * sA; B += z * sB; C += z * sC;

    const int tid = threadIdx.x, lane = tid & 31;
    const int wid = tid >> 5;
    const int wm = wid / WN, wn = wid % WN;

    float acc[MT][NTt][4] = {};

    auto load_stage = [&](int kt, int st) {
        const int k0 = kt * BK;
        __nv_bfloat16* As = AsBase + st * BM * AP;
        __nv_bfloat16* Bs = BsBase + st * BK * BP;
        #pragma unroll
        for (int i = tid; i < BM * BK / 8; i += NTH) {
            int r = i / (BK / 8), c = (i % (BK / 8)) * 8;
            cp_async16(As + r * AP + c, &A[(long long)(m0 + r) * ldA + k0 + c]);
        }
        #pragma unroll
        for (int i = tid; i < BK * BN / 8; i += NTH) {
            int r = i / (BN / 8), c = (i % (BN / 8)) * 8;
            cp_async16(Bs + r * BP + c, &B[(long long)(k0 + r) * ldB + n0 + c]);
        }
        asm volatile("cp.async.commit_group;");
    };

    #pragma unroll
    for (int s = 0; s < STAGES - 1; s++)
        if (s < KT) load_stage(s, s);

    for (int kt = 0; kt < KT; kt++) {
        const int st = kt % STAGES;
        if (kt + STAGES - 1 < KT) {
            load_stage(kt + STAGES - 1, (kt + STAGES - 1) % STAGES);
            asm volatile("cp.async.wait_group %0;" :: "n"(STAGES - 1));
        } else {
            asm volatile("cp.async.wait_group 0;");
        }
        __syncthreads();
        __nv_bfloat16* As = AsBase + st * BM * AP;
        __nv_bfloat16* Bs = BsBase + st * BK * BP;

        #pragma unroll
        for (int ks = 0; ks < BK / 16; ks++) {
            uint32_t a[MT][4], b[NTt][2];
            #pragma unroll
            for (int mt = 0; mt < MT; mt++) {
                uint32_t s = (uint32_t)__cvta_generic_to_shared(
                    As + (wm*WTM + mt*16 + (lane & 15)) * AP + ks*16 + ((lane >> 4) << 3));
                asm volatile("ldmatrix.sync.aligned.m8n8.x4.shared.b16 {%0,%1,%2,%3}, [%4];"
                    : "=r"(a[mt][0]), "=r"(a[mt][1]), "=r"(a[mt][2]), "=r"(a[mt][3])
                    : "r"(s));
            }
            #pragma unroll
            for (int np = 0; np < NTt / 2; np++) {
                uint32_t s = (uint32_t)__cvta_generic_to_shared(
                    Bs + (ks*16 + (lane & 15)) * BP + wn*WTN + np*16 + ((lane >> 4) << 3));
                asm volatile("ldmatrix.sync.aligned.m8n8.x4.trans.shared.b16 {%0,%1,%2,%3}, [%4];"
                    : "=r"(b[np*2][0]), "=r"(b[np*2][1]),
                      "=r"(b[np*2+1][0]), "=r"(b[np*2+1][1])
                    : "r"(s));
            }
            #pragma unroll
            for (int mt = 0; mt < MT; mt++)
                #pragma unroll
                for (int nt = 0; nt < NTt; nt++)
                    asm volatile(
                        "mma.sync.aligned.m16n8k16.row.col.f32.bf16.bf16.f32 "
                        "{%0,%1,%2,%3}, {%4,%5,%6,%7}, {%8,%9}, {%0,%1,%2,%3};"
                        : "+f"(acc[mt][nt][0]), "+f"(acc[mt][nt][1]),
                          "+f"(acc[mt][nt][2]), "+f"(acc[mt][nt][3])
                        : "r"(a[mt][0]), "r"(a[mt][1]), "r"(a[mt][2]), "r"(a[mt][3]),
                          "r"(b[nt][0]), "r"(b[nt][1]));
        }
        __syncthreads();
    }

    #pragma unroll
    for (int mt = 0; mt < MT; mt++) {
        int row = m0 + wm*WTM + mt*16 + (lane >> 2);
        #pragma unroll
        for (int nt = 0; nt < NTt; nt++) {
            int col = n0 + wn*WTN + nt*8 + ((lane & 3) << 1);
            float2* p0 = (float2*)&C[(long long)row * ldC + col];
            float2* p1 = (float2*)&C[(long long)(row + 8) * ldC + col];
            float2 v0 = make_float2(acc[mt][nt][0], acc[mt][nt][1]);
            float2 v1 = make_float2(acc[mt][nt][2], acc[mt][nt][3]);
            if (accumulate) {
                float2 o0 = *p0, o1 = *p1;
                v0.x += o0.x; v0.y += o0.y; v1.x += o1.x; v1.y += o1.y;
            }
            *p0 = v0; *p1 = v1;
        }
    }
}

// ----------------------------- rope cos/sin table --------------------------
__global__ void rope_table_kernel() {
    int s = blockIdx.x;
    int i = threadIdx.x;
    double invf = exp(-(double)i * (log(10000.0) / 32.0));
    double ang  = (double)s * invf;
    g_cs_tab[s*32 + i] = make_float2((float)cos(ang), (float)sin(ang));
}

// ------ RoPE + Hadamard phase; reads combined QKV; emits Qa split ----------
__global__ void rope_phase_kernel() {
    long long idx = (long long)blockIdx.x * blockDim.x + threadIdx.x;
    if (idx >= (long long)NTOK * HID) return;
    int d = (int)(idx & 63);
    int h = (int)((idx >> 6) & 15);
    int t = (int)(idx >> 10);
    int b = t >> 11;
    int s = t & (SEQ - 1);
    int step = s & 3;
    float sgn = hsign(step, d);

    long long qoff = (long long)t * 3072 + h * 64 + d;
    long long qpo  = (d < 32) ? qoff + 32 : qoff - 32;
    int i = d & 31;
    float2 cs = g_cs_tab[s*32 + i];

    float qv = g_QKV[qoff],        qp = g_QKV[qpo];
    float kv = g_QKV[qoff + 1024], kp = g_QKV[qpo + 1024];
    float vv = g_QKV[qoff + 2048];
    float qr = (d < 32) ? (qv*cs.x - qp*cs.y) : (qv*cs.x + qp*cs.y);
    float kr = (d < 32) ? (kv*cs.x - kp*cs.y) : (kv*cs.x + kp*cs.y);

    int bh = b*NH + h;
    long long hoff = (long long)(bh*SEQ + s) * HD + d;
    float qa = qr * sgn * 0.125f;
    g_Ks[hoff] = kr * sgn * 0.5f;
    g_Vs[hoff] = vv * sgn * 0.5f;

    __nv_bfloat16 qh = __float2bfloat16(qa);
    __nv_bfloat16 ql = __float2bfloat16(qa - __bfloat162float(qh));
    long long qbase = (long long)(bh*SEQ + s) * (3*HD) + d;
    g_Qas[qbase]        = qh;
    g_Qas[qbase + HD]   = qh;
    g_Qas[qbase + 2*HD] = ql;
}

// ---- full_K / full_V per slot; emits split B-operands for both GEMMs ------
__global__ void reduce_full_kernel() {
    int idx = blockIdx.x * blockDim.x + threadIdx.x;
    if (idx >= NBH*NS*HD) return;
    int d    = idx & 63;
    int slot = (idx >> 6) & (NS - 1);
    int bh   = idx >> 15;
    long long base = (long long)(bh*SEQ + slot*KF) * HD + d;
    float sk = 0.f, sv = 0.f;
    #pragma unroll
    for (int j = 0; j < KF; j++) { sk += g_Ks[base + j*HD]; sv += g_Vs[base + j*HD]; }
    g_fullV[idx] = sv;

    __nv_bfloat16 kh = __float2bfloat16(sk);
    __nv_bfloat16 kl = __float2bfloat16(sk - __bfloat162float(kh));
    long long ktb = ((long long)bh * (3*HD) + d) * NS + slot;
    g_KTs[ktb]                        = kh;
    g_KTs[ktb + (long long)HD * NS]   = kl;
    g_KTs[ktb + (long long)2*HD * NS] = kh;

    __nv_bfloat16 vh = __float2bfloat16(sv);
    __nv_bfloat16 vl = __float2bfloat16(sv - __bfloat162float(vh));
    long long fvb = ((long long)bh * (3*NS) + 3*slot) * HD + d;
    g_FVs[fvb]        = vh;
    g_FVs[fvb + HD]   = vl;
    g_FVs[fvb + 2*HD] = vh;
}

// --------- softmax per query (one warp); W split up to tile limit ----------
__global__ void softmax_kernel() {
    int warp = (blockIdx.x * blockDim.x + threadIdx.x) >> 5;
    int lane = threadIdx.x & 31;
    if (warp >= NBH*SEQ) return;
    int bh = warp / SEQ;
    int q  = warp - bh*SEQ;
    int slot = q >> 2, step = q & 3;

    const __nv_bfloat16* qrow = g_Qas + (long long)warp * (3*HD);
    float qa0 = __bfloat162float(qrow[lane])      + __bfloat162float(qrow[2*HD + lane]);
    float qa1 = __bfloat162float(qrow[32 + lane]) + __bfloat162float(qrow[2*HD + 32 + lane]);

    long long krow = (long long)(bh*SEQ + slot*KF) * HD;
    float pk0 = 0.f, pk1 = 0.f;
    for (int j = 0; j <= step; j++) {
        pk0 += g_Ks[krow + j*HD + lane];
        pk1 += g_Ks[krow + j*HD + lane + 32];
    }
    float cs = qa0*pk0 + qa1*pk1;
    #pragma unroll
    for (int o = 16; o; o >>= 1) cs += __shfl_xor_sync(0xFFFFFFFFu, cs, o);

    float* row = g_scores + (long long)bh*SEQ*NS + (long long)q*NS;

    float m = cs;
    for (int s = lane; s < slot; s += 32) m = fmaxf(m, row[s]);
    #pragma unroll
    for (int o = 16; o; o >>= 1) m = fmaxf(m, __shfl_xor_sync(0xFFFFFFFFu, m, o));

    float e_cs = expf(cs - m);
    float lsum = 0.f;
    for (int s = lane; s < slot; s += 32) {
        float e = expf(row[s] - m);
        row[s] = e;
        lsum += e;
    }
    #pragma unroll
    for (int o = 16; o; o >>= 1) lsum += __shfl_xor_sync(0xFFFFFFFFu, lsum, o);
    float inv = 1.0f / (lsum + e_cs);

    int smax_tile = (q | 127) >> 2;   // PV BK=32: 3*(smax+1) divisible, exact
    __nv_bfloat16* wrow = g_Ws + (long long)warp * (3*NS);
    for (int s = lane; s <= smax_tile; s += 32) {
        float w;
        if (s < slot)       w = row[s] * inv;
        else if (s == slot) w = e_cs * inv;
        else                w = 0.0f;
        __nv_bfloat16 h = __float2bfloat16(w);
        __nv_bfloat16 l = __float2bfloat16(w - __bfloat162float(h));
        wrow[3*s]     = h;
        wrow[3*s + 1] = h;
        wrow[3*s + 2] = l;
    }
    if (lane == 0) g_wcurr[warp] = e_cs * inv;
}

// --- fixup + output phase; writes O activations directly as hhl split ------
__global__ void fixup_kernel() {
    int bhq = blockIdx.x;
    int d = threadIdx.x;
    int bh = bhq >> 11;
    int q  = bhq & (SEQ - 1);
    int slot = q >> 2, step = q & 3;

    float out = g_Ohead[(long long)bhq * HD + d];
    long long vrow = (long long)(bh*SEQ + slot*KF) * HD + d;
    float pv = 0.f;
    for (int j = 0; j <= step; j++) pv += g_Vs[vrow + j*HD];
    float fv = g_fullV[((long long)bh*NS + slot) * HD + d];
    float wc = g_wcurr[bhq];
    float val = (out + wc * (pv - fv)) * hsign(step, d) * 2.0f;

    int b = bh >> 4, h = bh & 15;
    int t = b*SEQ + q;
    int c = h*HD + d;
    __nv_bfloat16 vh = __float2bfloat16(val);
    __nv_bfloat16 vl = __float2bfloat16(val - __bfloat162float(vh));
    long long base = (long long)t * 3072;
    g_Xs[base + c]        = vh;
    g_Xs[base + 1024 + c] = vh;
    g_Xs[base + 2048 + c] = vl;
}

// --------------------------------- launcher --------------------------------
extern "C" void kernel_launch(void* const* d_in, const int* in_sizes, int n_in,
                              void* d_out, int out_size)
{
    (void)in_sizes; (void)n_in; (void)out_size;
    const float* X  = (const float*)d_in[0];
    const float* Wq = (const float*)d_in[1];
    const float* Wk = (const float*)d_in[2];
    const float* Wv = (const float*)d_in[3];
    const float* Wo = (const float*)d_in[4];
    const float* Aq = (const float*)d_in[5];
    const float* Bq = (const float*)d_in[6];
    const float* Av = (const float*)d_in[7];
    const float* Bv = (const float*)d_in[8];
    const float* Ao = (const float*)d_in[9];
    const float* Bo = (const float*)d_in[10];
    float* Y = (float*)d_out;

    float *pQKV, *pXA, *pFV, *pSc, *pOh;
    __nv_bfloat16 *pXs, *pWqkv, *pWs, *pAB, *pBs, *pXAs, *pQas, *pKTs, *pFVs, *pWw;
    cudaGetSymbolAddress((void**)&pQKV, g_QKV);
    cudaGetSymbolAddress((void**)&pXA,  g_XA);
    cudaGetSymbolAddress((void**)&pFV,  g_fullV);
    cudaGetSymbolAddress((void**)&pSc,  g_scores);
    cudaGetSymbolAddress((void**)&pOh,  g_Ohead);
    cudaGetSymbolAddress((void**)&pXs,  g_Xs);
    cudaGetSymbolAddress((void**)&pWqkv, g_Wqkv);
    cudaGetSymbolAddress((void**)&pWs,  g_Wsplit);
    cudaGetSymbolAddress((void**)&pAB,  g_AB);
    cudaGetSymbolAddress((void**)&pBs,  g_Bsplit);
    cudaGetSymbolAddress((void**)&pXAs, g_XAsplit);
    cudaGetSymbolAddress((void**)&pQas, g_Qas);
    cudaGetSymbolAddress((void**)&pKTs, g_KTs);
    cudaGetSymbolAddress((void**)&pFVs, g_FVs);
    cudaGetSymbolAddress((void**)&pWw,  g_Ws);

    // dynamic smem (2 stages)
    const int SM_BIG = 2*(128*(64+8) + 64*(128+8))*2;   // 71680 B <128,128,64,2,4,2>
    const int SM_PV  = 2*(128*(32+8) + 32*(64+8))*2;    // 29696 B <128,64,32,4,2,2>
    cudaFuncSetAttribute(mma_gemm<128,128,64,2,4,2>,
                         cudaFuncAttributeMaxDynamicSharedMemorySize, SM_BIG);
    cudaFuncSetAttribute(mma_gemm<128,64,32,4,2,2>,
                         cudaFuncAttributeMaxDynamicSharedMemorySize, SM_PV);

    const int SPLIT_T = 256;
    #define GRID1D(n) (((n) + SPLIT_T - 1) / SPLIT_T)

    // ---- split X; assemble combined QKV weights + LoRA operands ----
    split_hhl<<<GRID1D(NTOK*HID), SPLIT_T>>>(X, pXs, NTOK, HID);
    split_hlh_off<<<GRID1D(HID*HID), SPLIT_T>>>(Wq, pWqkv, HID, HID, 3*HID, 0);
    split_hlh_off<<<GRID1D(HID*HID), SPLIT_T>>>(Wk, pWqkv, HID, HID, 3*HID, HID);
    split_hlh_off<<<GRID1D(HID*HID), SPLIT_T>>>(Wv, pWqkv, HID, HID, 3*HID, 2*HID);
    split_hlh_off<<<GRID1D(HID*LR), SPLIT_T>>>(Aq, pAB, HID, LR, 128, 0);
    split_hlh_off<<<GRID1D(HID*LR), SPLIT_T>>>(Av, pAB, HID, LR, 128, LR);
    split_hlh_off<<<GRID1D(LR*HID), SPLIT_T>>>(Bq, pBs, LR, HID, HID, 0);
    split_hlh_off<<<GRID1D(LR*HID), SPLIT_T>>>(Bv, pBs + (size_t)3*LR*HID, LR, HID, HID, 0);

    // ---- combined QKV projection ----
    {
        dim3 grid(3*HID/128, NTOK/128);   // 24 x 32
        mma_gemm<128,128,64,2,4,2><<<grid, 256, SM_BIG>>>(
            pXs, pWqkv, pQKV, NTOK, 3*HID, 3*HID, 3*HID, 3*HID, 3*HID,
            0,0,0, 0, 0);
    }
    // ---- LoRA stage-1 (q|v combined, N=128) ----
    {
        dim3 grid(1, NTOK/128);
        mma_gemm<128,128,64,2,4,2><<<grid, 256, SM_BIG>>>(
            pXs, pAB, pXA, NTOK, 128, 3*HID, 3*HID, 128, 128,
            0,0,0, 0, 0);
    }
    split_hhl2<<<GRID1D(NTOK*128), SPLIT_T>>>(pXA, pXAs);
    // ---- LoRA stage-2, batched z=2 (Q cols / V cols) ----
    {
        dim3 grid(HID/128, NTOK/128, 2);
        mma_gemm<128,128,64,2,4,2><<<grid, 256, SM_BIG>>>(
            pXAs, pBs, pQKV, NTOK, HID, 3*LR, 384, HID, 3*HID,
            192, (long long)3*LR*HID, 2048, 1, 0);
    }

    // ---- RoPE + phase (emits Qa split), slot reduction ----
    rope_table_kernel<<<SEQ, 32>>>();
    rope_phase_kernel<<<GRID1D(NTOK*HID), SPLIT_T>>>();
    reduce_full_kernel<<<GRID1D(NBH*NS*HD), SPLIT_T>>>();

    // ---- scores = Qa @ fullKT (batched, causal tile-skip) ----
    {
        dim3 grid(NS/128, SEQ/128, NBH);
        mma_gemm<128,128,64,2,4,2><<<grid, 256, SM_BIG>>>(
            pQas, pKTs, pSc, SEQ, NS, 3*HD, 3*HD, NS, NS,
            (long long)SEQ*3*HD, (long long)3*HD*NS, (long long)SEQ*NS,
            0, /*causal=*/1);
    }
    softmax_kernel<<<(NBH*SEQ*32)/256, 256>>>();

    // ---- Ohead = W @ fullV (batched, interleaved causal K-limit) ----
    {
        dim3 grid(1, SEQ/128, NBH);
        mma_gemm<128,64,32,4,2,2><<<grid, 256, SM_PV>>>(
            pWw, pFVs, pOh, SEQ, HD, 3*NS, 3*NS, HD, HD,
            (long long)SEQ*3*NS, (long long)3*NS*HD, (long long)SEQ*HD,
            0, /*causal=*/2);
    }
    // ---- fixup writes O activations directly in hhl split into g_Xs ----
    fixup_kernel<<<NBH*SEQ, HD>>>();

    // ---- O projection + LoRA ----
    split_hlh_off<<<GRID1D(HID*HID), SPLIT_T>>>(Wo, pWs, HID, HID, HID, 0);
    {
        dim3 grid(HID/128, NTOK/128);
        mma_gemm<128,128,64,2,4,2><<<grid, 256, SM_BIG>>>(
            pXs, pWs, Y, NTOK, HID, 3*HID, 3*HID, HID, HID,
            0,0,0, 0, 0);
    }
    split_hlh_off<<<GRID1D(HID*LR), SPLIT_T>>>(Ao, pAB, HID, LR, LR, 0);
    {
        dim3 grid(1, NTOK/128);   // N=64
        mma_gemm<128,64,32,4,2,2><<<grid, 256, SM_PV>>>(
            pXs, pAB, pXA, NTOK, LR, 3*HID, 3*HID, LR, LR,
            0,0,0, 0, 0);
    }
    split_hhl<<<GRID1D(NTOK*LR), SPLIT_T>>>(pXA, pXAs, NTOK, LR);
    split_hlh_off<<<GRID1D(LR*HID), SPLIT_T>>>(Bo, pBs, LR, HID, HID, 0);
    {
        dim3 grid(HID/128, NTOK/128);
        mma_gemm<128,128,64,2,4,2><<<grid, 256, SM_BIG>>>(
            pXAs, pBs, Y, NTOK, HID, 3*LR, 3*LR, HID, HID,
            0,0,0, 1, 0);
    }
    #undef GRID1D
}

// round 13
// speedup vs baseline: 1.1443x; 1.0293x over previous
#include <cuda_runtime.h>
#include <cuda_bf16.h>
#include <cstdint>
#include <cstddef>
#include <math.h>

// ---------------------------------------------------------------------------
// HoloKVAttention, all GEMMs bf16x3 split precision on tensor cores.
// R13: mega_prep (one launch for all input-only splits + rope table),
// LoRA stage-2 folded into QKV GEMM (K=3456) and O GEMM (K=3264) via
// K-extension. 13 launches total.
// ---------------------------------------------------------------------------

#define HID   1024
#define NH    16
#define HD    64
#define KF    4
#define LR    64
#define BATCH 2
#define SEQ   2048
#define NTOK  (BATCH*SEQ)   // 4096
#define NS    (SEQ/KF)      // 512
#define NBH   (BATCH*NH)    // 32
#define QK_LD 3456          // 3*HID + 2*3*LR
#define O_LD  3264          // 3*HID + 3*LR

// ------------------------- device scratch (static) -------------------------
__device__ float g_QKV[(size_t)NTOK*3*HID];   // [tok][Q|K|V]
__device__ float g_XA[NTOK*128];              // LoRA stage-1 out
__device__ float g_Ks[NBH*SEQ*HD];
__device__ float g_Vs[NBH*SEQ*HD];
__device__ float g_fullV[NBH*NS*HD];
__device__ float g_scores[(size_t)NBH*SEQ*NS];
__device__ float g_wcurr[NBH*SEQ];
__device__ float g_Ohead[NBH*SEQ*HD];
__device__ float2 g_cs_tab[SEQ*32];

// bf16 split operand buffers
__device__ __align__(16) __nv_bfloat16 g_XsQ[(size_t)NTOK*QK_LD];    // [Xh|Xh|Xl | XAq(h,h,l) | XAv(h,h,l)]
__device__ __align__(16) __nv_bfloat16 g_XsO[(size_t)NTOK*O_LD];     // [Oh|Oh|Ol | XAo(h,h,l)]
__device__ __align__(16) __nv_bfloat16 g_Wqkv2[(size_t)QK_LD*3*HID]; // [W hlh ; Bq-ext ; Bv-ext]
__device__ __align__(16) __nv_bfloat16 g_WoB[(size_t)O_LD*HID];      // [Wo hlh ; Bo hlh]
__device__ __align__(16) __nv_bfloat16 g_AB[3*HID*128];              // [Aq|Av] hlh, ld=128
__device__ __align__(16) __nv_bfloat16 g_ABo[3*HID*LR];              // Ao hlh, ld=64
__device__ __align__(16) __nv_bfloat16 g_Qas[(size_t)NBH*SEQ*3*HD];  // ld=192
__device__ __align__(16) __nv_bfloat16 g_KTs[(size_t)NBH*3*HD*NS];   // ld=NS
__device__ __align__(16) __nv_bfloat16 g_FVs[(size_t)NBH*3*NS*HD];   // interleaved, ld=HD
__device__ __align__(16) __nv_bfloat16 g_Ws[(size_t)NBH*SEQ*3*NS];   // ld=1536

__device__ __forceinline__ float hsign(int step, int col) {
    return ((0x6CA0 >> ((step << 2) | (col & 3))) & 1) ? -1.0f : 1.0f;
}

__device__ __forceinline__ void cp_async16(void* smem, const void* gmem) {
    uint32_t s = (uint32_t)__cvta_generic_to_shared(smem);
    asm volatile("cp.async.cg.shared.global [%0], [%1], 16;" :: "r"(s), "l"(gmem));
}

__device__ __forceinline__ void split2(float x, __nv_bfloat16& h, __nv_bfloat16& l) {
    h = __float2bfloat16(x);
    l = __float2bfloat16(x - __bfloat162float(h));
}

// ------------- mega prep: all input-only splits + rope table ---------------
// Segment sizes (in order):
//  S0  X hhl -> g_XsQ cols 0..3071              : NTOK*HID   = 4194304
//  S1  Wq/Wk/Wv hlh -> g_Wqkv2 rows 0..3071     : 3*HID*HID  = 3145728
//  S2  Aq/Av hlh -> g_AB                        : 2*HID*LR   = 131072
//  S3  Bq hlh -> g_Wqkv2 rows 3072.., cols 0..1023      : 65536
//  S4  Bv hlh -> g_Wqkv2 rows 3264.., cols 2048..3071   : 65536
//  S5  zeros: rows 3072..3263, cols 1024..3071  : 192*2048  = 393216
//  S6  zeros: rows 3264..3455, cols 0..2047     : 192*2048  = 393216
//  S7  Wo hlh -> g_WoB rows 0..3071             : HID*HID    = 1048576
//  S8  Bo hlh -> g_WoB rows 3072..              : LR*HID     = 65536
//  S9  Ao hlh -> g_ABo                          : HID*LR     = 65536
//  S10 rope table                               : SEQ*32     = 65536
#define MEGA_TOTAL (4194304+3145728+131072+65536+65536+393216+393216+1048576+65536+65536+65536)
__global__ void mega_prep(const float* __restrict__ X,
                          const float* __restrict__ Wq, const float* __restrict__ Wk,
                          const float* __restrict__ Wv, const float* __restrict__ Wo,
                          const float* __restrict__ Aq, const float* __restrict__ Bq,
                          const float* __restrict__ Av, const float* __restrict__ Bv,
                          const float* __restrict__ Ao, const float* __restrict__ Bo)
{
    int idx = blockIdx.x * blockDim.x + threadIdx.x;
    __nv_bfloat16 h, l;
    if (idx < 4194304) {                              // S0: X split
        int m = idx >> 10, k = idx & 1023;
        split2(X[idx], h, l);
        long long base = (long long)m * QK_LD;
        g_XsQ[base + k] = h; g_XsQ[base + 1024 + k] = h; g_XsQ[base + 2048 + k] = l;
        return;
    }
    idx -= 4194304;
    if (idx < 3145728) {                              // S1: Wq/Wk/Wv
        int sel = idx >> 20, off = idx & 1048575;
        int k = off >> 10, n = off & 1023;
        const float* src = (sel == 0) ? Wq : (sel == 1) ? Wk : Wv;
        split2(src[off], h, l);
        long long col = sel * 1024 + n;
        g_Wqkv2[(long long)k * 3072 + col]          = h;
        g_Wqkv2[(long long)(1024 + k) * 3072 + col] = l;
        g_Wqkv2[(long long)(2048 + k) * 3072 + col] = h;
        return;
    }
    idx -= 3145728;
    if (idx < 131072) {                               // S2: Aq/Av
        int sel = idx >> 16, off = idx & 65535;
        int k = off >> 6, n = off & 63;
        split2(((sel == 0) ? Aq : Av)[off], h, l);
        int col = sel * 64 + n;
        g_AB[k * 128 + col]          = h;
        g_AB[(1024 + k) * 128 + col] = l;
        g_AB[(2048 + k) * 128 + col] = h;
        return;
    }
    idx -= 131072;
    if (idx < 65536) {                                // S3: Bq
        int k = idx >> 10, n = idx & 1023;
        split2(Bq[idx], h, l);
        g_Wqkv2[(long long)(3072 + k) * 3072 + n] = h;
        g_Wqkv2[(long long)(3136 + k) * 3072 + n] = l;
        g_Wqkv2[(long long)(3200 + k) * 3072 + n] = h;
        return;
    }
    idx -= 65536;
    if (idx < 65536) {                                // S4: Bv
        int k = idx >> 10, n = idx & 1023;
        split2(Bv[idx], h, l);
        long long col = 2048 + n;
        g_Wqkv2[(long long)(3264 + k) * 3072 + col] = h;
        g_Wqkv2[(long long)(3328 + k) * 3072 + col] = l;
        g_Wqkv2[(long long)(3392 + k) * 3072 + col] = h;
        return;
    }
    idx -= 65536;
    if (idx < 393216) {                               // S5: zeros q-rows
        int r = idx / 2048, c = idx % 2048;
        g_Wqkv2[(long long)(3072 + r) * 3072 + 1024 + c] = __float2bfloat16(0.f);
        return;
    }
    idx -= 393216;
    if (idx < 393216) {                               // S6: zeros v-rows
        int r = idx / 2048, c = idx % 2048;
        g_Wqkv2[(long long)(3264 + r) * 3072 + c] = __float2bfloat16(0.f);
        return;
    }
    idx -= 393216;
    if (idx < 1048576) {                              // S7: Wo
        int k = idx >> 10, n = idx & 1023;
        split2(Wo[idx], h, l);
        g_WoB[(long long)k * 1024 + n]          = h;
        g_WoB[(long long)(1024 + k) * 1024 + n] = l;
        g_WoB[(long long)(2048 + k) * 1024 + n] = h;
        return;
    }
    idx -= 1048576;
    if (idx < 65536) {                                // S8: Bo
        int k = idx >> 10, n = idx & 1023;
        split2(Bo[idx], h, l);
        g_WoB[(long long)(3072 + k) * 1024 + n] = h;
        g_WoB[(long long)(3136 + k) * 1024 + n] = l;
        g_WoB[(long long)(3200 + k) * 1024 + n] = h;
        return;
    }
    idx -= 65536;
    if (idx < 65536) {                                // S9: Ao
        int k = idx >> 6, n = idx & 63;
        split2(Ao[idx], h, l);
        g_ABo[k * 64 + n]          = h;
        g_ABo[(1024 + k) * 64 + n] = l;
        g_ABo[(2048 + k) * 64 + n] = h;
        return;
    }
    idx -= 65536;
    {                                                 // S10: rope table
        int s = idx >> 5, i = idx & 31;
        double invf = exp(-(double)i * (log(10000.0) / 32.0));
        double ang  = (double)s * invf;
        g_cs_tab[s * 32 + i] = make_float2((float)cos(ang), (float)sin(ang));
    }
}

// XA [4096x128] -> g_XsQ cols 3072..3455: grp q at 3072 (h,h,l x64), v at 3264
__global__ void split_xa_qkv(const float* __restrict__ src) {
    int idx = blockIdx.x * blockDim.x + threadIdx.x;
    if (idx >= NTOK * 128) return;
    int m = idx >> 7, c = idx & 127;
    int grp = c >> 6, k = c & 63;
    __nv_bfloat16 h, l; split2(src[idx], h, l);
    long long base = (long long)m * QK_LD + 3072 + grp * 192;
    g_XsQ[base + k] = h; g_XsQ[base + 64 + k] = h; g_XsQ[base + 128 + k] = l;
}
// XAo [4096x64] -> g_XsO cols 3072..3263 (h,h,l)
__global__ void split_xa_o(const float* __restrict__ src) {
    int idx = blockIdx.x * blockDim.x + threadIdx.x;
    if (idx >= NTOK * 64) return;
    int m = idx >> 6, k = idx & 63;
    __nv_bfloat16 h, l; split2(src[idx], h, l);
    long long base = (long long)m * O_LD + 3072;
    g_XsO[base + k] = h; g_XsO[base + 64 + k] = h; g_XsO[base + 128 + k] = l;
}

// ---------- 2-stage cp.async bf16 tensor-core GEMM -------------------------
template<int BM, int BN, int BK, int WM, int WN, int STAGES>
__global__ __launch_bounds__(WM*WN*32)
void mma_gemm(const __nv_bfloat16* __restrict__ A,
              const __nv_bfloat16* __restrict__ B,
              float* __restrict__ C, int M, int N, int K,
              int ldA, int ldB, int ldC,
              long long sA, long long sB, long long sC,
              int accumulate, int causal)
{
    constexpr int NTH = WM * WN * 32;
    constexpr int WTM = BM / WM, WTN = BN / WN;
    constexpr int MT = WTM / 16, NTt = WTN / 8;
    constexpr int AP = BK + 8, BP = BN + 8;
    extern __shared__ __align__(16) __nv_bfloat16 smem[];
    __nv_bfloat16* AsBase = smem;
    __nv_bfloat16* BsBase = smem + STAGES * BM * AP;

    const int m0 = blockIdx.y * BM, n0 = blockIdx.x * BN;
    if (causal == 1 && n0 > ((m0 + BM - 1) >> 2)) return;
    int kend = K;
    if (causal == 2) {
        int kl = 3 * (((m0 + BM - 1) >> 2) + 1);
        kl = (kl + BK - 1) / BK * BK;
        if (kl < kend) kend = kl;
    }
    const int KT = kend / BK;

    const long long z = blockIdx.z;
    A += z * sA; B += z * sB; C += z * sC;

    const int tid = threadIdx.x, lane = tid & 31;
    const int wid = tid >> 5;
    const int wm = wid / WN, wn = wid % WN;

    float acc[MT][NTt][4] = {};

    auto load_stage = [&](int kt, int st) {
        const int k0 = kt * BK;
        __nv_bfloat16* As = AsBase + st * BM * AP;
        __nv_bfloat16* Bs = BsBase + st * BK * BP;
        #pragma unroll
        for (int i = tid; i < BM * BK / 8; i += NTH) {
            int r = i / (BK / 8), c = (i % (BK / 8)) * 8;
            cp_async16(As + r * AP + c, &A[(long long)(m0 + r) * ldA + k0 + c]);
        }
        #pragma unroll
        for (int i = tid; i < BK * BN / 8; i += NTH) {
            int r = i / (BN / 8), c = (i % (BN / 8)) * 8;
            cp_async16(Bs + r * BP + c, &B[(long long)(k0 + r) * ldB + n0 + c]);
        }
        asm volatile("cp.async.commit_group;");
    };

    #pragma unroll
    for (int s = 0; s < STAGES - 1; s++)
        if (s < KT) load_stage(s, s);

    for (int kt = 0; kt < KT; kt++) {
        const int st = kt % STAGES;
        if (kt + STAGES - 1 < KT) {
            load_stage(kt + STAGES - 1, (kt + STAGES - 1) % STAGES);
            asm volatile("cp.async.wait_group %0;" :: "n"(STAGES - 1));
        } else {
            asm volatile("cp.async.wait_group 0;");
        }
        __syncthreads();
        __nv_bfloat16* As = AsBase + st * BM * AP;
        __nv_bfloat16* Bs = BsBase + st * BK * BP;

        #pragma unroll
        for (int ks = 0; ks < BK / 16; ks++) {
            uint32_t a[MT][4], b[NTt][2];
            #pragma unroll
            for (int mt = 0; mt < MT; mt++) {
                uint32_t s = (uint32_t)__cvta_generic_to_shared(
                    As + (wm*WTM + mt*16 + (lane & 15)) * AP + ks*16 + ((lane >> 4) << 3));
                asm volatile("ldmatrix.sync.aligned.m8n8.x4.shared.b16 {%0,%1,%2,%3}, [%4];"
                    : "=r"(a[mt][0]), "=r"(a[mt][1]), "=r"(a[mt][2]), "=r"(a[mt][3])
                    : "r"(s));
            }
            #pragma unroll
            for (int np = 0; np < NTt / 2; np++) {
                uint32_t s = (uint32_t)__cvta_generic_to_shared(
                    Bs + (ks*16 + (lane & 15)) * BP + wn*WTN + np*16 + ((lane >> 4) << 3));
                asm volatile("ldmatrix.sync.aligned.m8n8.x4.trans.shared.b16 {%0,%1,%2,%3}, [%4];"
                    : "=r"(b[np*2][0]), "=r"(b[np*2][1]),
                      "=r"(b[np*2+1][0]), "=r"(b[np*2+1][1])
                    : "r"(s));
            }
            #pragma unroll
            for (int mt = 0; mt < MT; mt++)
                #pragma unroll
                for (int nt = 0; nt < NTt; nt++)
                    asm volatile(
                        "mma.sync.aligned.m16n8k16.row.col.f32.bf16.bf16.f32 "
                        "{%0,%1,%2,%3}, {%4,%5,%6,%7}, {%8,%9}, {%0,%1,%2,%3};"
                        : "+f"(acc[mt][nt][0]), "+f"(acc[mt][nt][1]),
                          "+f"(acc[mt][nt][2]), "+f"(acc[mt][nt][3])
                        : "r"(a[mt][0]), "r"(a[mt][1]), "r"(a[mt][2]), "r"(a[mt][3]),
                          "r"(b[nt][0]), "r"(b[nt][1]));
        }
        __syncthreads();
    }

    #pragma unroll
    for (int mt = 0; mt < MT; mt++) {
        int row = m0 + wm*WTM + mt*16 + (lane >> 2);
        #pragma unroll
        for (int nt = 0; nt < NTt; nt++) {
            int col = n0 + wn*WTN + nt*8 + ((lane & 3) << 1);
            float2* p0 = (float2*)&C[(long long)row * ldC + col];
            float2* p1 = (float2*)&C[(long long)(row + 8) * ldC + col];
            float2 v0 = make_float2(acc[mt][nt][0], acc[mt][nt][1]);
            float2 v1 = make_float2(acc[mt][nt][2], acc[mt][nt][3]);
            if (accumulate) {
                float2 o0 = *p0, o1 = *p1;
                v0.x += o0.x; v0.y += o0.y; v1.x += o1.x; v1.y += o1.y;
            }
            *p0 = v0; *p1 = v1;
        }
    }
}

// ------ RoPE + Hadamard phase; reads combined QKV; emits Qa split ----------
__global__ void rope_phase_kernel() {
    long long idx = (long long)blockIdx.x * blockDim.x + threadIdx.x;
    if (idx >= (long long)NTOK * HID) return;
    int d = (int)(idx & 63);
    int h = (int)((idx >> 6) & 15);
    int t = (int)(idx >> 10);
    int b = t >> 11;
    int s = t & (SEQ - 1);
    int step = s & 3;
    float sgn = hsign(step, d);

    long long qoff = (long long)t * 3072 + h * 64 + d;
    long long qpo  = (d < 32) ? qoff + 32 : qoff - 32;
    int i = d & 31;
    float2 cs = g_cs_tab[s*32 + i];

    float qv = g_QKV[qoff],        qp = g_QKV[qpo];
    float kv = g_QKV[qoff + 1024], kp = g_QKV[qpo + 1024];
    float vv = g_QKV[qoff + 2048];
    float qr = (d < 32) ? (qv*cs.x - qp*cs.y) : (qv*cs.x + qp*cs.y);
    float kr = (d < 32) ? (kv*cs.x - kp*cs.y) : (kv*cs.x + kp*cs.y);

    int bh = b*NH + h;
    long long hoff = (long long)(bh*SEQ + s) * HD + d;
    float qa = qr * sgn * 0.125f;
    g_Ks[hoff] = kr * sgn * 0.5f;
    g_Vs[hoff] = vv * sgn * 0.5f;

    __nv_bfloat16 qh, ql; split2(qa, qh, ql);
    long long qbase = (long long)(bh*SEQ + s) * (3*HD) + d;
    g_Qas[qbase]        = qh;
    g_Qas[qbase + HD]   = qh;
    g_Qas[qbase + 2*HD] = ql;
}

// ---- full_K / full_V per slot; emits split B-operands for both GEMMs ------
__global__ void reduce_full_kernel() {
    int idx = blockIdx.x * blockDim.x + threadIdx.x;
    if (idx >= NBH*NS*HD) return;
    int d    = idx & 63;
    int slot = (idx >> 6) & (NS - 1);
    int bh   = idx >> 15;
    long long base = (long long)(bh*SEQ + slot*KF) * HD + d;
    float sk = 0.f, sv = 0.f;
    #pragma unroll
    for (int j = 0; j < KF; j++) { sk += g_Ks[base + j*HD]; sv += g_Vs[base + j*HD]; }
    g_fullV[idx] = sv;

    __nv_bfloat16 kh, kl; split2(sk, kh, kl);
    long long ktb = ((long long)bh * (3*HD) + d) * NS + slot;
    g_KTs[ktb]                        = kh;
    g_KTs[ktb + (long long)HD * NS]   = kl;
    g_KTs[ktb + (long long)2*HD * NS] = kh;

    __nv_bfloat16 vh, vl; split2(sv, vh, vl);
    long long fvb = ((long long)bh * (3*NS) + 3*slot) * HD + d;
    g_FVs[fvb]        = vh;
    g_FVs[fvb + HD]   = vl;
    g_FVs[fvb + 2*HD] = vh;
}

// --------- softmax per query (one warp); W split up to tile limit ----------
__global__ void softmax_kernel() {
    int warp = (blockIdx.x * blockDim.x + threadIdx.x) >> 5;
    int lane = threadIdx.x & 31;
    if (warp >= NBH*SEQ) return;
    int bh = warp / SEQ;
    int q  = warp - bh*SEQ;
    int slot = q >> 2, step = q & 3;

    const __nv_bfloat16* qrow = g_Qas + (long long)warp * (3*HD);
    float qa0 = __bfloat162float(qrow[lane])      + __bfloat162float(qrow[2*HD + lane]);
    float qa1 = __bfloat162float(qrow[32 + lane]) + __bfloat162float(qrow[2*HD + 32 + lane]);

    long long krow = (long long)(bh*SEQ + slot*KF) * HD;
    float pk0 = 0.f, pk1 = 0.f;
    for (int j = 0; j <= step; j++) {
        pk0 += g_Ks[krow + j*HD + lane];
        pk1 += g_Ks[krow + j*HD + lane + 32];
    }
    float cs = qa0*pk0 + qa1*pk1;
    #pragma unroll
    for (int o = 16; o; o >>= 1) cs += __shfl_xor_sync(0xFFFFFFFFu, cs, o);

    float* row = g_scores + (long long)bh*SEQ*NS + (long long)q*NS;

    float m = cs;
    for (int s = lane; s < slot; s += 32) m = fmaxf(m, row[s]);
    #pragma unroll
    for (int o = 16; o; o >>= 1) m = fmaxf(m, __shfl_xor_sync(0xFFFFFFFFu, m, o));

    float e_cs = expf(cs - m);
    float lsum = 0.f;
    for (int s = lane; s < slot; s += 32) {
        float e = expf(row[s] - m);
        row[s] = e;
        lsum += e;
    }
    #pragma unroll
    for (int o = 16; o; o >>= 1) lsum += __shfl_xor_sync(0xFFFFFFFFu, lsum, o);
    float inv = 1.0f / (lsum + e_cs);

    int smax_tile = (q | 127) >> 2;   // PV BK=32: 3*(smax+1) divisible, exact
    __nv_bfloat16* wrow = g_Ws + (long long)warp * (3*NS);
    for (int s = lane; s <= smax_tile; s += 32) {
        float w;
        if (s < slot)       w = row[s] * inv;
        else if (s == slot) w = e_cs * inv;
        else                w = 0.0f;
        __nv_bfloat16 h, l; split2(w, h, l);
        wrow[3*s]     = h;
        wrow[3*s + 1] = h;
        wrow[3*s + 2] = l;
    }
    if (lane == 0) g_wcurr[warp] = e_cs * inv;
}

// --- fixup + output phase; writes O activations as hhl split into g_XsO ----
__global__ void fixup_kernel() {
    int bhq = blockIdx.x;
    int d = threadIdx.x;
    int bh = bhq >> 11;
    int q  = bhq & (SEQ - 1);
    int slot = q >> 2, step = q & 3;

    float out = g_Ohead[(long long)bhq * HD + d];
    long long vrow = (long long)(bh*SEQ + slot*KF) * HD + d;
    float pv = 0.f;
    for (int j = 0; j <= step; j++) pv += g_Vs[vrow + j*HD];
    float fv = g_fullV[((long long)bh*NS + slot) * HD + d];
    float wc = g_wcurr[bhq];
    float val = (out + wc * (pv - fv)) * hsign(step, d) * 2.0f;

    int b = bh >> 4, h = bh & 15;
    int t = b*SEQ + q;
    int c = h*HD + d;
    __nv_bfloat16 vh, vl; split2(val, vh, vl);
    long long base = (long long)t * O_LD;
    g_XsO[base + c]        = vh;
    g_XsO[base + 1024 + c] = vh;
    g_XsO[base + 2048 + c] = vl;
}

// --------------------------------- launcher --------------------------------
extern "C" void kernel_launch(void* const* d_in, const int* in_sizes, int n_in,
                              void* d_out, int out_size)
{
    (void)in_sizes; (void)n_in; (void)out_size;
    const float* X  = (const float*)d_in[0];
    const float* Wq = (const float*)d_in[1];
    const float* Wk = (const float*)d_in[2];
    const float* Wv = (const float*)d_in[3];
    const float* Wo = (const float*)d_in[4];
    const float* Aq = (const float*)d_in[5];
    const float* Bq = (const float*)d_in[6];
    const float* Av = (const float*)d_in[7];
    const float* Bv = (const float*)d_in[8];
    const float* Ao = (const float*)d_in[9];
    const float* Bo = (const float*)d_in[10];
    float* Y = (float*)d_out;

    float *pQKV, *pXA, *pSc, *pOh;
    __nv_bfloat16 *pXsQ, *pXsO, *pWqkv2, *pWoB, *pAB, *pABo, *pQas, *pKTs, *pFVs, *pWw;
    cudaGetSymbolAddress((void**)&pQKV,  g_QKV);
    cudaGetSymbolAddress((void**)&pXA,   g_XA);
    cudaGetSymbolAddress((void**)&pSc,   g_scores);
    cudaGetSymbolAddress((void**)&pOh,   g_Ohead);
    cudaGetSymbolAddress((void**)&pXsQ,  g_XsQ);
    cudaGetSymbolAddress((void**)&pXsO,  g_XsO);
    cudaGetSymbolAddress((void**)&pWqkv2, g_Wqkv2);
    cudaGetSymbolAddress((void**)&pWoB,  g_WoB);
    cudaGetSymbolAddress((void**)&pAB,   g_AB);
    cudaGetSymbolAddress((void**)&pABo,  g_ABo);
    cudaGetSymbolAddress((void**)&pQas,  g_Qas);
    cudaGetSymbolAddress((void**)&pKTs,  g_KTs);
    cudaGetSymbolAddress((void**)&pFVs,  g_FVs);
    cudaGetSymbolAddress((void**)&pWw,   g_Ws);

    const int SM_BIG = 2*(128*(64+8) + 64*(128+8))*2;   // 71680 B <128,128,64,2,4,2>
    const int SM_PV  = 2*(128*(32+8) + 32*(64+8))*2;    // 29696 B <128,64,32,4,2,2>
    cudaFuncSetAttribute(mma_gemm<128,128,64,2,4,2>,
                         cudaFuncAttributeMaxDynamicSharedMemorySize, SM_BIG);
    cudaFuncSetAttribute(mma_gemm<128,64,32,4,2,2>,
                         cudaFuncAttributeMaxDynamicSharedMemorySize, SM_PV);

    const int SPLIT_T = 256;
    #define GRID1D(n) (((n) + SPLIT_T - 1) / SPLIT_T)

    // 1) all input-only splits + rope table, one launch
    mega_prep<<<GRID1D(MEGA_TOTAL), SPLIT_T>>>(X, Wq, Wk, Wv, Wo, Aq, Bq, Av, Bv, Ao, Bo);

    // 2) LoRA stage-1 (q|v, N=128), K=3072 over g_XsQ
    {
        dim3 grid(1, NTOK/128);
        mma_gemm<128,128,64,2,4,2><<<grid, 256, SM_BIG>>>(
            pXsQ, pAB, pXA, NTOK, 128, 3*HID, QK_LD, 128, 128,
            0,0,0, 0, 0);
    }
    // 3) XA split appended into g_XsQ cols 3072..3455
    split_xa_qkv<<<GRID1D(NTOK*128), SPLIT_T>>>(pXA);
    // 4) combined QKV + LoRA projection, K=3456
    {
        dim3 grid(3*HID/128, NTOK/128);   // 24 x 32
        mma_gemm<128,128,64,2,4,2><<<grid, 256, SM_BIG>>>(
            pXsQ, pWqkv2, pQKV, NTOK, 3*HID, QK_LD, QK_LD, 3*HID, 3*HID,
            0,0,0, 0, 0);
    }

    // 5-6) RoPE + phase (emits Qa split), slot reduction
    rope_phase_kernel<<<GRID1D(NTOK*HID), SPLIT_T>>>();
    reduce_full_kernel<<<GRID1D(NBH*NS*HD), SPLIT_T>>>();

    // 7) scores = Qa @ fullKT (batched, causal tile-skip)
    {
        dim3 grid(NS/128, SEQ/128, NBH);
        mma_gemm<128,128,64,2,4,2><<<grid, 256, SM_BIG>>>(
            pQas, pKTs, pSc, SEQ, NS, 3*HD, 3*HD, NS, NS,
            (long long)SEQ*3*HD, (long long)3*HD*NS, (long long)SEQ*NS,
            0, /*causal=*/1);
    }
    // 8) softmax with current-slot override
    softmax_kernel<<<(NBH*SEQ*32)/256, 256>>>();

    // 9) Ohead = W @ fullV (batched, interleaved causal K-limit)
    {
        dim3 grid(1, SEQ/128, NBH);
        mma_gemm<128,64,32,4,2,2><<<grid, 256, SM_PV>>>(
            pWw, pFVs, pOh, SEQ, HD, 3*NS, 3*NS, HD, HD,
            (long long)SEQ*3*NS, (long long)3*NS*HD, (long long)SEQ*HD,
            0, /*causal=*/2);
    }
    // 10) fixup writes O activations in hhl split into g_XsO
    fixup_kernel<<<NBH*SEQ, HD>>>();

    // 11) LoRA-O stage-1 (N=64), K=3072 over g_XsO
    {
        dim3 grid(1, NTOK/128);
        mma_gemm<128,64,32,4,2,2><<<grid, 256, SM_PV>>>(
            pXsO, pABo, pXA, NTOK, LR, 3*HID, O_LD, LR, LR,
            0,0,0, 0, 0);
    }
    // 12) XAo split appended into g_XsO cols 3072..3263
    split_xa_o<<<GRID1D(NTOK*64), SPLIT_T>>>(pXA);
    // 13) combined O + LoRA projection, K=3264 -> Y
    {
        dim3 grid(HID/128, NTOK/128);
        mma_gemm<128,128,64,2,4,2><<<grid, 256, SM_BIG>>>(
            pXsO, pWoB, Y, NTOK, HID, O_LD, O_LD, HID, HID,
            0,0,0, 0, 0);
    }
    #undef GRID1D
}

// round 16
// speedup vs baseline: 1.1653x; 1.0183x over previous
#include <cuda_runtime.h>
#include <cuda_bf16.h>
#include <cstdint>
#include <cstddef>
#include <math.h>

// ---------------------------------------------------------------------------
// HoloKVAttention, all GEMMs bf16x3 split precision on mma.sync tensor cores.
// R16: revert to R13 base (tcgen05 unavailable: harness targets sm_100 without
// the 'a' ISA). Softmax now register-resident (one scores read, no write-back).
// ---------------------------------------------------------------------------

#define HID   1024
#define NH    16
#define HD    64
#define KF    4
#define LR    64
#define BATCH 2
#define SEQ   2048
#define NTOK  (BATCH*SEQ)   // 4096
#define NS    (SEQ/KF)      // 512
#define NBH   (BATCH*NH)    // 32
#define QK_LD 3456          // 3*HID + 2*3*LR
#define O_LD  3264          // 3*HID + 3*LR

// ------------------------- device scratch (static) -------------------------
__device__ float g_QKV[(size_t)NTOK*3*HID];   // [tok][Q|K|V]
__device__ float g_XA[NTOK*128];              // LoRA stage-1 out
__device__ float g_Ks[NBH*SEQ*HD];
__device__ float g_Vs[NBH*SEQ*HD];
__device__ float g_fullV[NBH*NS*HD];
__device__ float g_scores[(size_t)NBH*SEQ*NS];
__device__ float g_wcurr[NBH*SEQ];
__device__ float g_Ohead[NBH*SEQ*HD];
__device__ float2 g_cs_tab[SEQ*32];

// bf16 split operand buffers
__device__ __align__(16) __nv_bfloat16 g_XsQ[(size_t)NTOK*QK_LD];    // [Xh|Xh|Xl | XAq | XAv]
__device__ __align__(16) __nv_bfloat16 g_XsO[(size_t)NTOK*O_LD];     // [Oh|Oh|Ol | XAo]
__device__ __align__(16) __nv_bfloat16 g_Wqkv2[(size_t)QK_LD*3*HID]; // [W hlh ; Bq-ext ; Bv-ext]
__device__ __align__(16) __nv_bfloat16 g_WoB[(size_t)O_LD*HID];      // [Wo hlh ; Bo hlh]
__device__ __align__(16) __nv_bfloat16 g_AB[3*HID*128];              // [Aq|Av] hlh, ld=128
__device__ __align__(16) __nv_bfloat16 g_ABo[3*HID*LR];              // Ao hlh, ld=64
__device__ __align__(16) __nv_bfloat16 g_Qas[(size_t)NBH*SEQ*3*HD];  // ld=192
__device__ __align__(16) __nv_bfloat16 g_KTs[(size_t)NBH*3*HD*NS];   // ld=NS
__device__ __align__(16) __nv_bfloat16 g_FVs[(size_t)NBH*3*NS*HD];   // interleaved, ld=HD
__device__ __align__(16) __nv_bfloat16 g_Ws[(size_t)NBH*SEQ*3*NS];   // ld=1536

__device__ __forceinline__ float hsign(int step, int col) {
    return ((0x6CA0 >> ((step << 2) | (col & 3))) & 1) ? -1.0f : 1.0f;
}

__device__ __forceinline__ void cp_async16(void* smem_p, const void* gmem) {
    uint32_t s = (uint32_t)__cvta_generic_to_shared(smem_p);
    asm volatile("cp.async.cg.shared.global [%0], [%1], 16;" :: "r"(s), "l"(gmem));
}

__device__ __forceinline__ void split2(float x, __nv_bfloat16& h, __nv_bfloat16& l) {
    h = __float2bfloat16(x);
    l = __float2bfloat16(x - __bfloat162float(h));
}

// ------------- mega prep: all input-only splits + rope table ---------------
// S0  X hhl -> g_XsQ cols 0..3071              : 4194304
// S1  Wq/Wk/Wv hlh -> g_Wqkv2 rows 0..3071     : 3145728
// S2  Aq/Av hlh -> g_AB                        : 131072
// S3  Bq hlh -> g_Wqkv2 rows 3072.., cols 0..1023      : 65536
// S4  Bv hlh -> g_Wqkv2 rows 3264.., cols 2048..3071   : 65536
// S5  zeros: rows 3072..3263, cols 1024..3071  : 393216
// S6  zeros: rows 3264..3455, cols 0..2047     : 393216
// S7  Wo hlh -> g_WoB rows 0..3071             : 1048576
// S8  Bo hlh -> g_WoB rows 3072..              : 65536
// S9  Ao hlh -> g_ABo                          : 65536
// S10 rope table                               : 65536
#define MEGA_TOTAL (4194304+3145728+131072+65536+65536+393216+393216+1048576+65536+65536+65536)
__global__ void mega_prep(const float* __restrict__ X,
                          const float* __restrict__ Wq, const float* __restrict__ Wk,
                          const float* __restrict__ Wv, const float* __restrict__ Wo,
                          const float* __restrict__ Aq, const float* __restrict__ Bq,
                          const float* __restrict__ Av, const float* __restrict__ Bv,
                          const float* __restrict__ Ao, const float* __restrict__ Bo)
{
    int idx = blockIdx.x * blockDim.x + threadIdx.x;
    __nv_bfloat16 h, l;
    if (idx < 4194304) {                              // S0: X split
        int m = idx >> 10, k = idx & 1023;
        split2(X[idx], h, l);
        long long base = (long long)m * QK_LD;
        g_XsQ[base + k] = h; g_XsQ[base + 1024 + k] = h; g_XsQ[base + 2048 + k] = l;
        return;
    }
    idx -= 4194304;
    if (idx < 3145728) {                              // S1: Wq/Wk/Wv
        int sel = idx >> 20, off = idx & 1048575;
        int k = off >> 10, n = off & 1023;
        const float* src = (sel == 0) ? Wq : (sel == 1) ? Wk : Wv;
        split2(src[off], h, l);
        long long col = sel * 1024 + n;
        g_Wqkv2[(long long)k * 3072 + col]          = h;
        g_Wqkv2[(long long)(1024 + k) * 3072 + col] = l;
        g_Wqkv2[(long long)(2048 + k) * 3072 + col] = h;
        return;
    }
    idx -= 3145728;
    if (idx < 131072) {                               // S2: Aq/Av
        int sel = idx >> 16, off = idx & 65535;
        int k = off >> 6, n = off & 63;
        split2(((sel == 0) ? Aq : Av)[off], h, l);
        int col = sel * 64 + n;
        g_AB[k * 128 + col]          = h;
        g_AB[(1024 + k) * 128 + col] = l;
        g_AB[(2048 + k) * 128 + col] = h;
        return;
    }
    idx -= 131072;
    if (idx < 65536) {                                // S3: Bq
        int k = idx >> 10, n = idx & 1023;
        split2(Bq[idx], h, l);
        g_Wqkv2[(long long)(3072 + k) * 3072 + n] = h;
        g_Wqkv2[(long long)(3136 + k) * 3072 + n] = l;
        g_Wqkv2[(long long)(3200 + k) * 3072 + n] = h;
        return;
    }
    idx -= 65536;
    if (idx < 65536) {                                // S4: Bv
        int k = idx >> 10, n = idx & 1023;
        split2(Bv[idx], h, l);
        long long col = 2048 + n;
        g_Wqkv2[(long long)(3264 + k) * 3072 + col] = h;
        g_Wqkv2[(long long)(3328 + k) * 3072 + col] = l;
        g_Wqkv2[(long long)(3392 + k) * 3072 + col] = h;
        return;
    }
    idx -= 65536;
    if (idx < 393216) {                               // S5: zeros q-rows
        int r = idx / 2048, c = idx % 2048;
        g_Wqkv2[(long long)(3072 + r) * 3072 + 1024 + c] = __float2bfloat16(0.f);
        return;
    }
    idx -= 393216;
    if (idx < 393216) {                               // S6: zeros v-rows
        int r = idx / 2048, c = idx % 2048;
        g_Wqkv2[(long long)(3264 + r) * 3072 + c] = __float2bfloat16(0.f);
        return;
    }
    idx -= 393216;
    if (idx < 1048576) {                              // S7: Wo
        int k = idx >> 10, n = idx & 1023;
        split2(Wo[idx], h, l);
        g_WoB[(long long)k * 1024 + n]          = h;
        g_WoB[(long long)(1024 + k) * 1024 + n] = l;
        g_WoB[(long long)(2048 + k) * 1024 + n] = h;
        return;
    }
    idx -= 1048576;
    if (idx < 65536) {                                // S8: Bo
        int k = idx >> 10, n = idx & 1023;
        split2(Bo[idx], h, l);
        g_WoB[(long long)(3072 + k) * 1024 + n] = h;
        g_WoB[(long long)(3136 + k) * 1024 + n] = l;
        g_WoB[(long long)(3200 + k) * 1024 + n] = h;
        return;
    }
    idx -= 65536;
    if (idx < 65536) {                                // S9: Ao
        int k = idx >> 6, n = idx & 63;
        split2(Ao[idx], h, l);
        g_ABo[k * 64 + n]          = h;
        g_ABo[(1024 + k) * 64 + n] = l;
        g_ABo[(2048 + k) * 64 + n] = h;
        return;
    }
    idx -= 65536;
    {                                                 // S10: rope table
        int s = idx >> 5, i = idx & 31;
        double invf = exp(-(double)i * (log(10000.0) / 32.0));
        double ang  = (double)s * invf;
        g_cs_tab[s * 32 + i] = make_float2((float)cos(ang), (float)sin(ang));
    }
}

// XA [4096x128] -> g_XsQ cols 3072..3455
__global__ void split_xa_qkv(const float* __restrict__ src) {
    int idx = blockIdx.x * blockDim.x + threadIdx.x;
    if (idx >= NTOK * 128) return;
    int m = idx >> 7, c = idx & 127;
    int grp = c >> 6, k = c & 63;
    __nv_bfloat16 h, l; split2(src[idx], h, l);
    long long base = (long long)m * QK_LD + 3072 + grp * 192;
    g_XsQ[base + k] = h; g_XsQ[base + 64 + k] = h; g_XsQ[base + 128 + k] = l;
}
// XAo [4096x64] -> g_XsO cols 3072..3263
__global__ void split_xa_o(const float* __restrict__ src) {
    int idx = blockIdx.x * blockDim.x + threadIdx.x;
    if (idx >= NTOK * 64) return;
    int m = idx >> 6, k = idx & 63;
    __nv_bfloat16 h, l; split2(src[idx], h, l);
    long long base = (long long)m * O_LD + 3072;
    g_XsO[base + k] = h; g_XsO[base + 64 + k] = h; g_XsO[base + 128 + k] = l;
}

// ---------- 2-stage cp.async bf16 mma.sync tensor-core GEMM ----------------
template<int BM, int BN, int BK, int WM, int WN, int STAGES>
__global__ __launch_bounds__(WM*WN*32)
void mma_gemm(const __nv_bfloat16* __restrict__ A,
              const __nv_bfloat16* __restrict__ B,
              float* __restrict__ C, int M, int N, int K,
              int ldA, int ldB, int ldC,
              long long sA, long long sB, long long sC,
              int accumulate, int causal)
{
    constexpr int NTH = WM * WN * 32;
    constexpr int WTM = BM / WM, WTN = BN / WN;
    constexpr int MT = WTM / 16, NTt = WTN / 8;
    constexpr int AP = BK + 8, BP = BN + 8;
    extern __shared__ __align__(16) __nv_bfloat16 smem[];
    __nv_bfloat16* AsBase = smem;
    __nv_bfloat16* BsBase = smem + STAGES * BM * AP;

    const int m0 = blockIdx.y * BM, n0 = blockIdx.x * BN;
    if (causal == 1 && n0 > ((m0 + BM - 1) >> 2)) return;
    int kend = K;
    if (causal == 2) {
        int kl = 3 * (((m0 + BM - 1) >> 2) + 1);
        kl = (kl + BK - 1) / BK * BK;
        if (kl < kend) kend = kl;
    }
    const int KT = kend / BK;

    const long long z = blockIdx.z;
    A += z * sA; B += z * sB; C += z * sC;

    const int tid = threadIdx.x, lane = tid & 31;
    const int wid = tid >> 5;
    const int wm = wid / WN, wn = wid % WN;

    float acc[MT][NTt][4] = {};

    auto load_stage = [&](int kt, int st) {
        const int k0 = kt * BK;
        __nv_bfloat16* As = AsBase + st * BM * AP;
        __nv_bfloat16* Bs = BsBase + st * BK * BP;
        #pragma unroll
        for (int i = tid; i < BM * BK / 8; i += NTH) {
            int r = i / (BK / 8), c = (i % (BK / 8)) * 8;
            cp_async16(As + r * AP + c, &A[(long long)(m0 + r) * ldA + k0 + c]);
        }
        #pragma unroll
        for (int i = tid; i < BK * BN / 8; i += NTH) {
            int r = i / (BN / 8), c = (i % (BN / 8)) * 8;
            cp_async16(Bs + r * BP + c, &B[(long long)(k0 + r) * ldB + n0 + c]);
        }
        asm volatile("cp.async.commit_group;");
    };

    #pragma unroll
    for (int s = 0; s < STAGES - 1; s++)
        if (s < KT) load_stage(s, s);

    for (int kt = 0; kt < KT; kt++) {
        const int st = kt % STAGES;
        if (kt + STAGES - 1 < KT) {
            load_stage(kt + STAGES - 1, (kt + STAGES - 1) % STAGES);
            asm volatile("cp.async.wait_group %0;" :: "n"(STAGES - 1));
        } else {
            asm volatile("cp.async.wait_group 0;");
        }
        __syncthreads();
        __nv_bfloat16* As = AsBase + st * BM * AP;
        __nv_bfloat16* Bs = BsBase + st * BK * BP;

        #pragma unroll
        for (int ks = 0; ks < BK / 16; ks++) {
            uint32_t a[MT][4], b[NTt][2];
            #pragma unroll
            for (int mt = 0; mt < MT; mt++) {
                uint32_t s = (uint32_t)__cvta_generic_to_shared(
                    As + (wm*WTM + mt*16 + (lane & 15)) * AP + ks*16 + ((lane >> 4) << 3));
                asm volatile("ldmatrix.sync.aligned.m8n8.x4.shared.b16 {%0,%1,%2,%3}, [%4];"
                    : "=r"(a[mt][0]), "=r"(a[mt][1]), "=r"(a[mt][2]), "=r"(a[mt][3])
                    : "r"(s));
            }
            #pragma unroll
            for (int np = 0; np < NTt / 2; np++) {
                uint32_t s = (uint32_t)__cvta_generic_to_shared(
                    Bs + (ks*16 + (lane & 15)) * BP + wn*WTN + np*16 + ((lane >> 4) << 3));
                asm volatile("ldmatrix.sync.aligned.m8n8.x4.trans.shared.b16 {%0,%1,%2,%3}, [%4];"
                    : "=r"(b[np*2][0]), "=r"(b[np*2][1]),
                      "=r"(b[np*2+1][0]), "=r"(b[np*2+1][1])
                    : "r"(s));
            }
            #pragma unroll
            for (int mt = 0; mt < MT; mt++)
                #pragma unroll
                for (int nt = 0; nt < NTt; nt++)
                    asm volatile(
                        "mma.sync.aligned.m16n8k16.row.col.f32.bf16.bf16.f32 "
                        "{%0,%1,%2,%3}, {%4,%5,%6,%7}, {%8,%9}, {%0,%1,%2,%3};"
                        : "+f"(acc[mt][nt][0]), "+f"(acc[mt][nt][1]),
                          "+f"(acc[mt][nt][2]), "+f"(acc[mt][nt][3])
                        : "r"(a[mt][0]), "r"(a[mt][1]), "r"(a[mt][2]), "r"(a[mt][3]),
                          "r"(b[nt][0]), "r"(b[nt][1]));
        }
        __syncthreads();
    }

    #pragma unroll
    for (int mt = 0; mt < MT; mt++) {
        int row = m0 + wm*WTM + mt*16 + (lane >> 2);
        #pragma unroll
        for (int nt = 0; nt < NTt; nt++) {
            int col = n0 + wn*WTN + nt*8 + ((lane & 3) << 1);
            float2* p0 = (float2*)&C[(long long)row * ldC + col];
            float2* p1 = (float2*)&C[(long long)(row + 8) * ldC + col];
            float2 v0 = make_float2(acc[mt][nt][0], acc[mt][nt][1]);
            float2 v1 = make_float2(acc[mt][nt][2], acc[mt][nt][3]);
            if (accumulate) {
                float2 o0 = *p0, o1 = *p1;
                v0.x += o0.x; v0.y += o0.y; v1.x += o1.x; v1.y += o1.y;
            }
            *p0 = v0; *p1 = v1;
        }
    }
}

// ------ RoPE + Hadamard phase; reads combined QKV; emits Qa split ----------
__global__ void rope_phase_kernel() {
    long long idx = (long long)blockIdx.x * blockDim.x + threadIdx.x;
    if (idx >= (long long)NTOK * HID) return;
    int d = (int)(idx & 63);
    int h = (int)((idx >> 6) & 15);
    int t = (int)(idx >> 10);
    int b = t >> 11;
    int s = t & (SEQ - 1);
    int step = s & 3;
    float sgn = hsign(step, d);

    long long qoff = (long long)t * 3072 + h * 64 + d;
    long long qpo  = (d < 32) ? qoff + 32 : qoff - 32;
    int i = d & 31;
    float2 cs = g_cs_tab[s*32 + i];

    float qv = g_QKV[qoff],        qp = g_QKV[qpo];
    float kv = g_QKV[qoff + 1024], kp = g_QKV[qpo + 1024];
    float vv = g_QKV[qoff + 2048];
    float qr = (d < 32) ? (qv*cs.x - qp*cs.y) : (qv*cs.x + qp*cs.y);
    float kr = (d < 32) ? (kv*cs.x - kp*cs.y) : (kv*cs.x + kp*cs.y);

    int bh = b*NH + h;
    long long hoff = (long long)(bh*SEQ + s) * HD + d;
    float qa = qr * sgn * 0.125f;
    g_Ks[hoff] = kr * sgn * 0.5f;
    g_Vs[hoff] = vv * sgn * 0.5f;

    __nv_bfloat16 qh, ql; split2(qa, qh, ql);
    long long qbase = (long long)(bh*SEQ + s) * (3*HD) + d;
    g_Qas[qbase]        = qh;
    g_Qas[qbase + HD]   = qh;
    g_Qas[qbase + 2*HD] = ql;
}

// ---- full_K / full_V per slot; emits split B-operands for both GEMMs ------
__global__ void reduce_full_kernel() {
    int idx = blockIdx.x * blockDim.x + threadIdx.x;
    if (idx >= NBH*NS*HD) return;
    int d    = idx & 63;
    int slot = (idx >> 6) & (NS - 1);
    int bh   = idx >> 15;
    long long base = (long long)(bh*SEQ + slot*KF) * HD + d;
    float sk = 0.f, sv = 0.f;
    #pragma unroll
    for (int j = 0; j < KF; j++) { sk += g_Ks[base + j*HD]; sv += g_Vs[base + j*HD]; }
    g_fullV[idx] = sv;

    __nv_bfloat16 kh, kl; split2(sk, kh, kl);
    long long ktb = ((long long)bh * (3*HD) + d) * NS + slot;
    g_KTs[ktb]                        = kh;
    g_KTs[ktb + (long long)HD * NS]   = kl;
    g_KTs[ktb + (long long)2*HD * NS] = kh;

    __nv_bfloat16 vh, vl; split2(sv, vh, vl);
    long long fvb = ((long long)bh * (3*NS) + 3*slot) * HD + d;
    g_FVs[fvb]        = vh;
    g_FVs[fvb + HD]   = vl;
    g_FVs[fvb + 2*HD] = vh;
}

// --------- softmax per query (one warp); register-resident row -------------
__global__ void softmax_kernel() {
    int warp = (blockIdx.x * blockDim.x + threadIdx.x) >> 5;
    int lane = threadIdx.x & 31;
    if (warp >= NBH*SEQ) return;
    int bh = warp / SEQ;
    int q  = warp - bh*SEQ;
    int slot = q >> 2, step = q & 3;

    const __nv_bfloat16* qrow = g_Qas + (long long)warp * (3*HD);
    float qa0 = __bfloat162float(qrow[lane])      + __bfloat162float(qrow[2*HD + lane]);
    float qa1 = __bfloat162float(qrow[32 + lane]) + __bfloat162float(qrow[2*HD + 32 + lane]);

    long long krow = (long long)(bh*SEQ + slot*KF) * HD;
    float pk0 = 0.f, pk1 = 0.f;
    for (int j = 0; j <= step; j++) {
        pk0 += g_Ks[krow + j*HD + lane];
        pk1 += g_Ks[krow + j*HD + lane + 32];
    }
    float cs = qa0*pk0 + qa1*pk1;
    #pragma unroll
    for (int o = 16; o; o >>= 1) cs += __shfl_xor_sync(0xFFFFFFFFu, cs, o);

    const float* row = g_scores + (long long)bh*SEQ*NS + (long long)q*NS;

    // load this lane's slots into registers (<= 16 of them), single pass
    float v[16];
    #pragma unroll
    for (int i = 0; i < 16; i++) {
        int s = lane + i*32;
        v[i] = (s < slot) ? row[s] : -INFINITY;
    }

    float m = cs;
    #pragma unroll
    for (int i = 0; i < 16; i++) m = fmaxf(m, v[i]);
    #pragma unroll
    for (int o = 16; o; o >>= 1) m = fmaxf(m, __shfl_xor_sync(0xFFFFFFFFu, m, o));

    float e_cs = expf(cs - m);
    float lsum = 0.f;
    #pragma unroll
    for (int i = 0; i < 16; i++) {
        float e = expf(v[i] - m);   // exp(-inf) = 0 for masked slots
        v[i] = e;
        lsum += e;
    }
    #pragma unroll
    for (int o = 16; o; o >>= 1) lsum += __shfl_xor_sync(0xFFFFFFFFu, lsum, o);
    float inv = 1.0f / (lsum + e_cs);

    int smax_tile = (q | 127) >> 2;   // PV BK=32: 3*(smax+1) divisible, exact
    __nv_bfloat16* wrow = g_Ws + (long long)warp * (3*NS);
    #pragma unroll
    for (int i = 0; i < 16; i++) {
        int s = lane + i*32;
        if (s > smax_tile) continue;
        float w;
        if (s < slot)       w = v[i] * inv;
        else if (s == slot) w = e_cs * inv;
        else                w = 0.0f;
        __nv_bfloat16 h, l; split2(w, h, l);
        wrow[3*s]     = h;
        wrow[3*s + 1] = h;
        wrow[3*s + 2] = l;
    }
    if (lane == 0) g_wcurr[warp] = e_cs * inv;
}

// --- fixup + output phase; writes O activations as hhl split into g_XsO ----
__global__ void fixup_kernel() {
    int bhq = blockIdx.x;
    int d = threadIdx.x;
    int bh = bhq >> 11;
    int q  = bhq & (SEQ - 1);
    int slot = q >> 2, step = q & 3;

    float out = g_Ohead[(long long)bhq * HD + d];
    long long vrow = (long long)(bh*SEQ + slot*KF) * HD + d;
    float pv = 0.f;
    for (int j = 0; j <= step; j++) pv += g_Vs[vrow + j*HD];
    float fv = g_fullV[((long long)bh*NS + slot) * HD + d];
    float wc = g_wcurr[bhq];
    float val = (out + wc * (pv - fv)) * hsign(step, d) * 2.0f;

    int b = bh >> 4, h = bh & 15;
    int t = b*SEQ + q;
    int c = h*HD + d;
    __nv_bfloat16 vh, vl; split2(val, vh, vl);
    long long base = (long long)t * O_LD;
    g_XsO[base + c]        = vh;
    g_XsO[base + 1024 + c] = vh;
    g_XsO[base + 2048 + c] = vl;
}

// --------------------------------- launcher --------------------------------
extern "C" void kernel_launch(void* const* d_in, const int* in_sizes, int n_in,
                              void* d_out, int out_size)
{
    (void)in_sizes; (void)n_in; (void)out_size;
    const float* X  = (const float*)d_in[0];
    const float* Wq = (const float*)d_in[1];
    const float* Wk = (const float*)d_in[2];
    const float* Wv = (const float*)d_in[3];
    const float* Wo = (const float*)d_in[4];
    const float* Aq = (const float*)d_in[5];
    const float* Bq = (const float*)d_in[6];
    const float* Av = (const float*)d_in[7];
    const float* Bv = (const float*)d_in[8];
    const float* Ao = (const float*)d_in[9];
    const float* Bo = (const float*)d_in[10];
    float* Y = (float*)d_out;

    float *pQKV, *pXA, *pSc, *pOh;
    __nv_bfloat16 *pXsQ, *pXsO, *pWqkv2, *pWoB, *pAB, *pABo, *pQas, *pKTs, *pFVs, *pWw;
    cudaGetSymbolAddress((void**)&pQKV,  g_QKV);
    cudaGetSymbolAddress((void**)&pXA,   g_XA);
    cudaGetSymbolAddress((void**)&pSc,   g_scores);
    cudaGetSymbolAddress((void**)&pOh,   g_Ohead);
    cudaGetSymbolAddress((void**)&pXsQ,  g_XsQ);
    cudaGetSymbolAddress((void**)&pXsO,  g_XsO);
    cudaGetSymbolAddress((void**)&pWqkv2, g_Wqkv2);
    cudaGetSymbolAddress((void**)&pWoB,  g_WoB);
    cudaGetSymbolAddress((void**)&pAB,   g_AB);
    cudaGetSymbolAddress((void**)&pABo,  g_ABo);
    cudaGetSymbolAddress((void**)&pQas,  g_Qas);
    cudaGetSymbolAddress((void**)&pKTs,  g_KTs);
    cudaGetSymbolAddress((void**)&pFVs,  g_FVs);
    cudaGetSymbolAddress((void**)&pWw,   g_Ws);

    const int SM_BIG = 2*(128*(64+8) + 64*(128+8))*2;   // 71680 B <128,128,64,2,4,2>
    const int SM_PV  = 2*(128*(32+8) + 32*(64+8))*2;    // 29696 B <128,64,32,4,2,2>
    cudaFuncSetAttribute(mma_gemm<128,128,64,2,4,2>,
                         cudaFuncAttributeMaxDynamicSharedMemorySize, SM_BIG);
    cudaFuncSetAttribute(mma_gemm<128,64,32,4,2,2>,
                         cudaFuncAttributeMaxDynamicSharedMemorySize, SM_PV);

    const int SPLIT_T = 256;
    #define GRID1D(n) (((n) + SPLIT_T - 1) / SPLIT_T)

    // 1) all input-only splits + rope table, one launch
    mega_prep<<<GRID1D(MEGA_TOTAL), SPLIT_T>>>(X, Wq, Wk, Wv, Wo, Aq, Bq, Av, Bv, Ao, Bo);

    // 2) LoRA stage-1 (q|v, N=128), K=3072 over g_XsQ
    {
        dim3 grid(1, NTOK/128);
        mma_gemm<128,128,64,2,4,2><<<grid, 256, SM_BIG>>>(
            pXsQ, pAB, pXA, NTOK, 128, 3*HID, QK_LD, 128, 128,
            0,0,0, 0, 0);
    }
    // 3) XA split appended into g_XsQ cols 3072..3455
    split_xa_qkv<<<GRID1D(NTOK*128), SPLIT_T>>>(pXA);
    // 4) combined QKV + LoRA projection, K=3456
    {
        dim3 grid(3*HID/128, NTOK/128);   // 24 x 32
        mma_gemm<128,128,64,2,4,2><<<grid, 256, SM_BIG>>>(
            pXsQ, pWqkv2, pQKV, NTOK, 3*HID, QK_LD, QK_LD, 3*HID, 3*HID,
            0,0,0, 0, 0);
    }

    // 5-6) RoPE + phase (emits Qa split), slot reduction
    rope_phase_kernel<<<GRID1D(NTOK*HID), SPLIT_T>>>();
    reduce_full_kernel<<<GRID1D(NBH*NS*HD), SPLIT_T>>>();

    // 7) scores = Qa @ fullKT (batched, causal tile-skip)
    {
        dim3 grid(NS/128, SEQ/128, NBH);
        mma_gemm<128,128,64,2,4,2><<<grid, 256, SM_BIG>>>(
            pQas, pKTs, pSc, SEQ, NS, 3*HD, 3*HD, NS, NS,
            (long long)SEQ*3*HD, (long long)3*HD*NS, (long long)SEQ*NS,
            0, /*causal=*/1);
    }
    // 8) softmax with current-slot override (register-resident)
    softmax_kernel<<<(NBH*SEQ*32)/256, 256>>>();

    // 9) Ohead = W @ fullV (batched, interleaved causal K-limit)
    {
        dim3 grid(1, SEQ/128, NBH);
        mma_gemm<128,64,32,4,2,2><<<grid, 256, SM_PV>>>(
            pWw, pFVs, pOh, SEQ, HD, 3*NS, 3*NS, HD, HD,
            (long long)SEQ*3*NS, (long long)3*NS*HD, (long long)SEQ*HD,
            0, /*causal=*/2);
    }
    // 10) fixup writes O activations in hhl split into g_XsO
    fixup_kernel<<<NBH*SEQ, HD>>>();

    // 11) LoRA-O stage-1 (N=64), K=3072 over g_XsO
    {
        dim3 grid(1, NTOK/128);
        mma_gemm<128,64,32,4,2,2><<<grid, 256, SM_PV>>>(
            pXsO, pABo, pXA, NTOK, LR, 3*HID, O_LD, LR, LR,
            0,0,0, 0, 0);
    }
    // 12) XAo split appended into g_XsO cols 3072..3263
    split_xa_o<<<GRID1D(NTOK*64), SPLIT_T>>>(pXA);
    // 13) combined O + LoRA projection, K=3264 -> Y
    {
        dim3 grid(HID/128, NTOK/128);
        mma_gemm<128,128,64,2,4,2><<<grid, 256, SM_BIG>>>(
            pXsO, pWoB, Y, NTOK, HID, O_LD, O_LD, HID, HID,
            0,0,0, 0, 0);
    }
    #undef GRID1D
}

// round 17
// speedup vs baseline: 1.2486x; 1.0715x over previous
#include <cuda_runtime.h>
#include <cuda_bf16.h>
#include <cstdint>
#include <cstddef>
#include <math.h>

// ---------------------------------------------------------------------------
// HoloKVAttention, all GEMMs bf16x3 split precision on mma.sync tensor cores.
// R17: all elementwise kernels vectorized to 16B/8B transactions (identical
// arithmetic to R16). GEMMs unchanged.
// ---------------------------------------------------------------------------

#define HID   1024
#define NH    16
#define HD    64
#define KF    4
#define LR    64
#define BATCH 2
#define SEQ   2048
#define NTOK  (BATCH*SEQ)   // 4096
#define NS    (SEQ/KF)      // 512
#define NBH   (BATCH*NH)    // 32
#define QK_LD 3456          // 3*HID + 2*3*LR
#define O_LD  3264          // 3*HID + 3*LR

// ------------------------- device scratch (static) -------------------------
__device__ float g_QKV[(size_t)NTOK*3*HID];
__device__ float g_XA[NTOK*128];
__device__ float g_Ks[NBH*SEQ*HD];
__device__ float g_Vs[NBH*SEQ*HD];
__device__ float g_fullV[NBH*NS*HD];
__device__ float g_scores[(size_t)NBH*SEQ*NS];
__device__ float g_wcurr[NBH*SEQ];
__device__ float g_Ohead[NBH*SEQ*HD];
__device__ float2 g_cs_tab[SEQ*32];

__device__ __align__(16) __nv_bfloat16 g_XsQ[(size_t)NTOK*QK_LD];
__device__ __align__(16) __nv_bfloat16 g_XsO[(size_t)NTOK*O_LD];
__device__ __align__(16) __nv_bfloat16 g_Wqkv2[(size_t)QK_LD*3*HID];
__device__ __align__(16) __nv_bfloat16 g_WoB[(size_t)O_LD*HID];
__device__ __align__(16) __nv_bfloat16 g_AB[3*HID*128];
__device__ __align__(16) __nv_bfloat16 g_ABo[3*HID*LR];
__device__ __align__(16) __nv_bfloat16 g_Qas[(size_t)NBH*SEQ*3*HD];
__device__ __align__(16) __nv_bfloat16 g_KTs[(size_t)NBH*3*HD*NS];
__device__ __align__(16) __nv_bfloat16 g_FVs[(size_t)NBH*3*NS*HD];
__device__ __align__(16) __nv_bfloat16 g_Ws[(size_t)NBH*SEQ*3*NS];

__device__ __forceinline__ float hsign(int step, int col) {
    return ((0x6CA0 >> ((step << 2) | (col & 3))) & 1) ? -1.0f : 1.0f;
}

__device__ __forceinline__ void cp_async16(void* smem_p, const void* gmem) {
    uint32_t s = (uint32_t)__cvta_generic_to_shared(smem_p);
    asm volatile("cp.async.cg.shared.global [%0], [%1], 16;" :: "r"(s), "l"(gmem));
}

__device__ __forceinline__ void split2(float x, __nv_bfloat16& h, __nv_bfloat16& l) {
    h = __float2bfloat16(x);
    l = __float2bfloat16(x - __bfloat162float(h));
}
// 8 floats -> 8 hi bf16 (uint4) + 8 lo bf16 (uint4)
__device__ __forceinline__ void split8(float4 a, float4 b, uint4& H, uint4& L) {
    float v[8] = {a.x, a.y, a.z, a.w, b.x, b.y, b.z, b.w};
    uint32_t hh[4], ll[4];
    #pragma unroll
    for (int i = 0; i < 4; i++) {
        __nv_bfloat16 h0, l0, h1, l1;
        split2(v[2*i], h0, l0); split2(v[2*i+1], h1, l1);
        hh[i] = (uint32_t)__bfloat16_as_ushort(h0) | ((uint32_t)__bfloat16_as_ushort(h1) << 16);
        ll[i] = (uint32_t)__bfloat16_as_ushort(l0) | ((uint32_t)__bfloat16_as_ushort(l1) << 16);
    }
    H = make_uint4(hh[0], hh[1], hh[2], hh[3]);
    L = make_uint4(ll[0], ll[1], ll[2], ll[3]);
}
// 4 floats -> 4 hi bf16 (uint2) + 4 lo bf16 (uint2)
__device__ __forceinline__ void split4(const float* v, uint2& H, uint2& L) {
    uint32_t hh[2], ll[2];
    #pragma unroll
    for (int i = 0; i < 2; i++) {
        __nv_bfloat16 h0, l0, h1, l1;
        split2(v[2*i], h0, l0); split2(v[2*i+1], h1, l1);
        hh[i] = (uint32_t)__bfloat16_as_ushort(h0) | ((uint32_t)__bfloat16_as_ushort(h1) << 16);
        ll[i] = (uint32_t)__bfloat16_as_ushort(l0) | ((uint32_t)__bfloat16_as_ushort(l1) << 16);
    }
    H = make_uint2(hh[0], hh[1]);
    L = make_uint2(ll[0], ll[1]);
}

// ------------- mega prep (vectorized): splits + rope table -----------------
// V0  X split 8-wide          : 524288
// V1  Wq/Wk/Wv 8-wide         : 393216
// V7  Wo 8-wide               : 131072
// V2  Aq/Av 8-wide            : 16384
// V3  Bq 8-wide               : 8192
// V4  Bv 8-wide               : 8192
// V5  zeros q-rows 8-wide     : 49152
// V6  zeros v-rows 8-wide     : 49152
// V8  Bo 8-wide               : 8192
// V9  Ao 8-wide               : 8192
// V10 rope table scalar       : 65536
#define MEGA_TOTAL (524288+393216+131072+16384+8192+8192+49152+49152+8192+8192+65536)
__global__ void mega_prep(const float* __restrict__ X,
                          const float* __restrict__ Wq, const float* __restrict__ Wk,
                          const float* __restrict__ Wv, const float* __restrict__ Wo,
                          const float* __restrict__ Aq, const float* __restrict__ Bq,
                          const float* __restrict__ Av, const float* __restrict__ Bv,
                          const float* __restrict__ Ao, const float* __restrict__ Bo)
{
    int v = blockIdx.x * blockDim.x + threadIdx.x;
    uint4 H, L;
    if (v < 524288) {                                 // V0: X split
        int m = v >> 7, c8 = (v & 127) << 3;
        float4 a = *(const float4*)&X[m*1024 + c8];
        float4 b = *(const float4*)&X[m*1024 + c8 + 4];
        split8(a, b, H, L);
        long long base = (long long)m * QK_LD;
        *(uint4*)&g_XsQ[base + c8]        = H;
        *(uint4*)&g_XsQ[base + 1024 + c8] = H;
        *(uint4*)&g_XsQ[base + 2048 + c8] = L;
        return;
    }
    v -= 524288;
    if (v < 393216) {                                 // V1: Wq/Wk/Wv hlh
        int sel = v / 131072, off = v % 131072;
        int k = off >> 7, n8 = (off & 127) << 3;
        const float* src = (sel == 0) ? Wq : (sel == 1) ? Wk : Wv;
        float4 a = *(const float4*)&src[k*1024 + n8];
        float4 b = *(const float4*)&src[k*1024 + n8 + 4];
        split8(a, b, H, L);
        long long col = sel * 1024 + n8;
        *(uint4*)&g_Wqkv2[(long long)k * 3072 + col]          = H;
        *(uint4*)&g_Wqkv2[(long long)(1024 + k) * 3072 + col] = L;
        *(uint4*)&g_Wqkv2[(long long)(2048 + k) * 3072 + col] = H;
        return;
    }
    v -= 393216;
    if (v < 131072) {                                 // V7: Wo hlh
        int k = v >> 7, n8 = (v & 127) << 3;
        float4 a = *(const float4*)&Wo[k*1024 + n8];
        float4 b = *(const float4*)&Wo[k*1024 + n8 + 4];
        split8(a, b, H, L);
        *(uint4*)&g_WoB[(long long)k * 1024 + n8]          = H;
        *(uint4*)&g_WoB[(long long)(1024 + k) * 1024 + n8] = L;
        *(uint4*)&g_WoB[(long long)(2048 + k) * 1024 + n8] = H;
        return;
    }
    v -= 131072;
    if (v < 16384) {                                  // V2: Aq/Av hlh
        int sel = v >> 13, off = v & 8191;
        int k = off >> 3, n8 = (off & 7) << 3;
        const float* src = (sel == 0) ? Aq : Av;
        float4 a = *(const float4*)&src[k*64 + n8];
        float4 b = *(const float4*)&src[k*64 + n8 + 4];
        split8(a, b, H, L);
        int col = sel * 64 + n8;
        *(uint4*)&g_AB[k * 128 + col]          = H;
        *(uint4*)&g_AB[(1024 + k) * 128 + col] = L;
        *(uint4*)&g_AB[(2048 + k) * 128 + col] = H;
        return;
    }
    v -= 16384;
    if (v < 8192) {                                   // V3: Bq hlh
        int k = v >> 7, n8 = (v & 127) << 3;
        float4 a = *(const float4*)&Bq[k*1024 + n8];
        float4 b = *(const float4*)&Bq[k*1024 + n8 + 4];
        split8(a, b, H, L);
        *(uint4*)&g_Wqkv2[(long long)(3072 + k) * 3072 + n8] = H;
        *(uint4*)&g_Wqkv2[(long long)(3136 + k) * 3072 + n8] = L;
        *(uint4*)&g_Wqkv2[(long long)(3200 + k) * 3072 + n8] = H;
        return;
    }
    v -= 8192;
    if (v < 8192) {                                   // V4: Bv hlh
        int k = v >> 7, n8 = (v & 127) << 3;
        float4 a = *(const float4*)&Bv[k*1024 + n8];
        float4 b = *(const float4*)&Bv[k*1024 + n8 + 4];
        split8(a, b, H, L);
        long long col = 2048 + n8;
        *(uint4*)&g_Wqkv2[(long long)(3264 + k) * 3072 + col] = H;
        *(uint4*)&g_Wqkv2[(long long)(3328 + k) * 3072 + col] = L;
        *(uint4*)&g_Wqkv2[(long long)(3392 + k) * 3072 + col] = H;
        return;
    }
    v -= 8192;
    if (v < 49152) {                                  // V5: zeros q-rows
        int r = v >> 8, c8 = (v & 255) << 3;
        uint4 z = make_uint4(0, 0, 0, 0);
        *(uint4*)&g_Wqkv2[(long long)(3072 + r) * 3072 + 1024 + c8] = z;
        return;
    }
    v -= 49152;
    if (v < 49152) {                                  // V6: zeros v-rows
        int r = v >> 8, c8 = (v & 255) << 3;
        uint4 z = make_uint4(0, 0, 0, 0);
        *(uint4*)&g_Wqkv2[(long long)(3264 + r) * 3072 + c8] = z;
        return;
    }
    v -= 49152;
    if (v < 8192) {                                   // V8: Bo hlh
        int k = v >> 7, n8 = (v & 127) << 3;
        float4 a = *(const float4*)&Bo[k*1024 + n8];
        float4 b = *(const float4*)&Bo[k*1024 + n8 + 4];
        split8(a, b, H, L);
        *(uint4*)&g_WoB[(long long)(3072 + k) * 1024 + n8] = H;
        *(uint4*)&g_WoB[(long long)(3136 + k) * 1024 + n8] = L;
        *(uint4*)&g_WoB[(long long)(3200 + k) * 1024 + n8] = H;
        return;
    }
    v -= 8192;
    if (v < 8192) {                                   // V9: Ao hlh
        int k = v >> 3, n8 = (v & 7) << 3;
        float4 a = *(const float4*)&Ao[k*64 + n8];
        float4 b = *(const float4*)&Ao[k*64 + n8 + 4];
        split8(a, b, H, L);
        *(uint4*)&g_ABo[k * 64 + n8]          = H;
        *(uint4*)&g_ABo[(1024 + k) * 64 + n8] = L;
        *(uint4*)&g_ABo[(2048 + k) * 64 + n8] = H;
        return;
    }
    v -= 8192;
    {                                                 // V10: rope table
        int s = v >> 5, i = v & 31;
        double invf = exp(-(double)i * (log(10000.0) / 32.0));
        double ang  = (double)s * invf;
        g_cs_tab[s * 32 + i] = make_float2((float)cos(ang), (float)sin(ang));
    }
}

// XA [4096x128] -> g_XsQ cols 3072..3455 (8-wide)
__global__ void split_xa_qkv(const float* __restrict__ src) {
    int idx = blockIdx.x * blockDim.x + threadIdx.x;
    if (idx >= NTOK * 16) return;
    int m = idx >> 4, g8 = idx & 15;
    int grp = g8 >> 3, k8 = (g8 & 7) << 3;
    float4 a = *(const float4*)&src[m*128 + grp*64 + k8];
    float4 b = *(const float4*)&src[m*128 + grp*64 + k8 + 4];
    uint4 H, L; split8(a, b, H, L);
    long long base = (long long)m * QK_LD + 3072 + grp * 192;
    *(uint4*)&g_XsQ[base + k8]       = H;
    *(uint4*)&g_XsQ[base + 64 + k8]  = H;
    *(uint4*)&g_XsQ[base + 128 + k8] = L;
}
// XAo [4096x64] -> g_XsO cols 3072..3263 (8-wide)
__global__ void split_xa_o(const float* __restrict__ src) {
    int idx = blockIdx.x * blockDim.x + threadIdx.x;
    if (idx >= NTOK * 8) return;
    int m = idx >> 3, k8 = (idx & 7) << 3;
    float4 a = *(const float4*)&src[m*64 + k8];
    float4 b = *(const float4*)&src[m*64 + k8 + 4];
    uint4 H, L; split8(a, b, H, L);
    long long base = (long long)m * O_LD + 3072;
    *(uint4*)&g_XsO[base + k8]       = H;
    *(uint4*)&g_XsO[base + 64 + k8]  = H;
    *(uint4*)&g_XsO[base + 128 + k8] = L;
}

// ---------- 2-stage cp.async bf16 mma.sync tensor-core GEMM ----------------
template<int BM, int BN, int BK, int WM, int WN, int STAGES>
__global__ __launch_bounds__(WM*WN*32)
void mma_gemm(const __nv_bfloat16* __restrict__ A,
              const __nv_bfloat16* __restrict__ B,
              float* __restrict__ C, int M, int N, int K,
              int ldA, int ldB, int ldC,
              long long sA, long long sB, long long sC,
              int accumulate, int causal)
{
    constexpr int NTH = WM * WN * 32;
    constexpr int WTM = BM / WM, WTN = BN / WN;
    constexpr int MT = WTM / 16, NTt = WTN / 8;
    constexpr int AP = BK + 8, BP = BN + 8;
    extern __shared__ __align__(16) __nv_bfloat16 smem[];
    __nv_bfloat16* AsBase = smem;
    __nv_bfloat16* BsBase = smem + STAGES * BM * AP;

    const int m0 = blockIdx.y * BM, n0 = blockIdx.x * BN;
    if (causal == 1 && n0 > ((m0 + BM - 1) >> 2)) return;
    int kend = K;
    if (causal == 2) {
        int kl = 3 * (((m0 + BM - 1) >> 2) + 1);
        kl = (kl + BK - 1) / BK * BK;
        if (kl < kend) kend = kl;
    }
    const int KT = kend / BK;

    const long long z = blockIdx.z;
    A += z * sA; B += z * sB; C += z * sC;

    const int tid = threadIdx.x, lane = tid & 31;
    const int wid = tid >> 5;
    const int wm = wid / WN, wn = wid % WN;

    float acc[MT][NTt][4] = {};

    auto load_stage = [&](int kt, int st) {
        const int k0 = kt * BK;
        __nv_bfloat16* As = AsBase + st * BM * AP;
        __nv_bfloat16* Bs = BsBase + st * BK * BP;
        #pragma unroll
        for (int i = tid; i < BM * BK / 8; i += NTH) {
            int r = i / (BK / 8), c = (i % (BK / 8)) * 8;
            cp_async16(As + r * AP + c, &A[(long long)(m0 + r) * ldA + k0 + c]);
        }
        #pragma unroll
        for (int i = tid; i < BK * BN / 8; i += NTH) {
            int r = i / (BN / 8), c = (i % (BN / 8)) * 8;
            cp_async16(Bs + r * BP + c, &B[(long long)(k0 + r) * ldB + n0 + c]);
        }
        asm volatile("cp.async.commit_group;");
    };

    #pragma unroll
    for (int s = 0; s < STAGES - 1; s++)
        if (s < KT) load_stage(s, s);

    for (int kt = 0; kt < KT; kt++) {
        const int st = kt % STAGES;
        if (kt + STAGES - 1 < KT) {
            load_stage(kt + STAGES - 1, (kt + STAGES - 1) % STAGES);
            asm volatile("cp.async.wait_group %0;" :: "n"(STAGES - 1));
        } else {
            asm volatile("cp.async.wait_group 0;");
        }
        __syncthreads();
        __nv_bfloat16* As = AsBase + st * BM * AP;
        __nv_bfloat16* Bs = BsBase + st * BK * BP;

        #pragma unroll
        for (int ks = 0; ks < BK / 16; ks++) {
            uint32_t a[MT][4], b[NTt][2];
            #pragma unroll
            for (int mt = 0; mt < MT; mt++) {
                uint32_t s = (uint32_t)__cvta_generic_to_shared(
                    As + (wm*WTM + mt*16 + (lane & 15)) * AP + ks*16 + ((lane >> 4) << 3));
                asm volatile("ldmatrix.sync.aligned.m8n8.x4.shared.b16 {%0,%1,%2,%3}, [%4];"
                    : "=r"(a[mt][0]), "=r"(a[mt][1]), "=r"(a[mt][2]), "=r"(a[mt][3])
                    : "r"(s));
            }
            #pragma unroll
            for (int np = 0; np < NTt / 2; np++) {
                uint32_t s = (uint32_t)__cvta_generic_to_shared(
                    Bs + (ks*16 + (lane & 15)) * BP + wn*WTN + np*16 + ((lane >> 4) << 3));
                asm volatile("ldmatrix.sync.aligned.m8n8.x4.trans.shared.b16 {%0,%1,%2,%3}, [%4];"
                    : "=r"(b[np*2][0]), "=r"(b[np*2][1]),
                      "=r"(b[np*2+1][0]), "=r"(b[np*2+1][1])
                    : "r"(s));
            }
            #pragma unroll
            for (int mt = 0; mt < MT; mt++)
                #pragma unroll
                for (int nt = 0; nt < NTt; nt++)
                    asm volatile(
                        "mma.sync.aligned.m16n8k16.row.col.f32.bf16.bf16.f32 "
                        "{%0,%1,%2,%3}, {%4,%5,%6,%7}, {%8,%9}, {%0,%1,%2,%3};"
                        : "+f"(acc[mt][nt][0]), "+f"(acc[mt][nt][1]),
                          "+f"(acc[mt][nt][2]), "+f"(acc[mt][nt][3])
                        : "r"(a[mt][0]), "r"(a[mt][1]), "r"(a[mt][2]), "r"(a[mt][3]),
                          "r"(b[nt][0]), "r"(b[nt][1]));
        }
        __syncthreads();
    }

    #pragma unroll
    for (int mt = 0; mt < MT; mt++) {
        int row = m0 + wm*WTM + mt*16 + (lane >> 2);
        #pragma unroll
        for (int nt = 0; nt < NTt; nt++) {
            int col = n0 + wn*WTN + nt*8 + ((lane & 3) << 1);
            float2* p0 = (float2*)&C[(long long)row * ldC + col];
            float2* p1 = (float2*)&C[(long long)(row + 8) * ldC + col];
            float2 v0 = make_float2(acc[mt][nt][0], acc[mt][nt][1]);
            float2 v1 = make_float2(acc[mt][nt][2], acc[mt][nt][3]);
            if (accumulate) {
                float2 o0 = *p0, o1 = *p1;
                v0.x += o0.x; v0.y += o0.y; v1.x += o1.x; v1.y += o1.y;
            }
            *p0 = v0; *p1 = v1;
        }
    }
}

// ------ RoPE + Hadamard phase (4-wide); emits Qa split ---------------------
__global__ void rope_phase_kernel() {
    int idx = blockIdx.x * blockDim.x + threadIdx.x;   // NTOK*HID/4 = 1048576
    if (idx >= NTOK * HID / 4) return;
    int d  = (idx & 15) << 2;          // 0,4,...,60 (never crosses 32)
    int h  = (idx >> 4) & 15;
    int t  = idx >> 8;
    int b  = t >> 11;
    int s  = t & (SEQ - 1);
    int step = s & 3;

    long long gbase = (long long)t * 3072 + h * 64;
    int dp = (d < 32) ? d + 32 : d - 32;
    float4 qv = *(const float4*)&g_QKV[gbase + d];
    float4 qp = *(const float4*)&g_QKV[gbase + dp];
    float4 kv = *(const float4*)&g_QKV[gbase + 1024 + d];
    float4 kp = *(const float4*)&g_QKV[gbase + 1024 + dp];
    float4 vv = *(const float4*)&g_QKV[gbase + 2048 + d];

    float qvv[4] = {qv.x, qv.y, qv.z, qv.w};
    float qpp[4] = {qp.x, qp.y, qp.z, qp.w};
    float kvv[4] = {kv.x, kv.y, kv.z, kv.w};
    float kpp[4] = {kp.x, kp.y, kp.z, kp.w};
    float vvv[4] = {vv.x, vv.y, vv.z, vv.w};

    int i0 = d & 31;
    float qa[4], ks[4], vs[4];
    #pragma unroll
    for (int j = 0; j < 4; j++) {
        float2 cs = g_cs_tab[s*32 + i0 + j];
        float sgn = hsign(step, d + j);
        float qr = (d < 32) ? (qvv[j]*cs.x - qpp[j]*cs.y) : (qvv[j]*cs.x + qpp[j]*cs.y);
        float kr = (d < 32) ? (kvv[j]*cs.x - kpp[j]*cs.y) : (kvv[j]*cs.x + kpp[j]*cs.y);
        qa[j] = qr * sgn * 0.125f;
        ks[j] = kr * sgn * 0.5f;
        vs[j] = vvv[j] * sgn * 0.5f;
    }

    int bh = b*NH + h;
    long long hoff = (long long)(bh*SEQ + s) * HD + d;
    *(float4*)&g_Ks[hoff] = make_float4(ks[0], ks[1], ks[2], ks[3]);
    *(float4*)&g_Vs[hoff] = make_float4(vs[0], vs[1], vs[2], vs[3]);

    uint2 H, L; split4(qa, H, L);
    long long qbase = (long long)(bh*SEQ + s) * (3*HD) + d;
    *(uint2*)&g_Qas[qbase]        = H;
    *(uint2*)&g_Qas[qbase + HD]   = H;
    *(uint2*)&g_Qas[qbase + 2*HD] = L;
}

// ---- full_K / full_V per slot; emits split B-operands ---------------------
__global__ void reduce_full_kernel() {
    int idx = blockIdx.x * blockDim.x + threadIdx.x;
    if (idx >= NBH*NS*HD) return;
    int d    = idx & 63;
    int slot = (idx >> 6) & (NS - 1);
    int bh   = idx >> 15;
    long long base = (long long)(bh*SEQ + slot*KF) * HD + d;
    float sk = 0.f, sv = 0.f;
    #pragma unroll
    for (int j = 0; j < KF; j++) { sk += g_Ks[base + j*HD]; sv += g_Vs[base + j*HD]; }
    g_fullV[idx] = sv;

    __nv_bfloat16 kh, kl; split2(sk, kh, kl);
    long long ktb = ((long long)bh * (3*HD) + d) * NS + slot;
    g_KTs[ktb]                        = kh;
    g_KTs[ktb + (long long)HD * NS]   = kl;
    g_KTs[ktb + (long long)2*HD * NS] = kh;

    __nv_bfloat16 vh, vl; split2(sv, vh, vl);
    long long fvb = ((long long)bh * (3*NS) + 3*slot) * HD + d;
    g_FVs[fvb]        = vh;
    g_FVs[fvb + HD]   = vl;
    g_FVs[fvb + 2*HD] = vh;
}

// --------- softmax per query (one warp); register-resident row -------------
__global__ void softmax_kernel() {
    int warp = (blockIdx.x * blockDim.x + threadIdx.x) >> 5;
    int lane = threadIdx.x & 31;
    if (warp >= NBH*SEQ) return;
    int bh = warp / SEQ;
    int q  = warp - bh*SEQ;
    int slot = q >> 2, step = q & 3;

    const __nv_bfloat16* qrow = g_Qas + (long long)warp * (3*HD);
    float qa0 = __bfloat162float(qrow[lane])      + __bfloat162float(qrow[2*HD + lane]);
    float qa1 = __bfloat162float(qrow[32 + lane]) + __bfloat162float(qrow[2*HD + 32 + lane]);

    long long krow = (long long)(bh*SEQ + slot*KF) * HD;
    float pk0 = 0.f, pk1 = 0.f;
    for (int j = 0; j <= step; j++) {
        pk0 += g_Ks[krow + j*HD + lane];
        pk1 += g_Ks[krow + j*HD + lane + 32];
    }
    float cs = qa0*pk0 + qa1*pk1;
    #pragma unroll
    for (int o = 16; o; o >>= 1) cs += __shfl_xor_sync(0xFFFFFFFFu, cs, o);

    const float* row = g_scores + (long long)bh*SEQ*NS + (long long)q*NS;

    float v[16];
    #pragma unroll
    for (int i = 0; i < 16; i++) {
        int s = lane + i*32;
        v[i] = (s < slot) ? row[s] : -INFINITY;
    }

    float m = cs;
    #pragma unroll
    for (int i = 0; i < 16; i++) m = fmaxf(m, v[i]);
    #pragma unroll
    for (int o = 16; o; o >>= 1) m = fmaxf(m, __shfl_xor_sync(0xFFFFFFFFu, m, o));

    float e_cs = expf(cs - m);
    float lsum = 0.f;
    #pragma unroll
    for (int i = 0; i < 16; i++) {
        float e = expf(v[i] - m);
        v[i] = e;
        lsum += e;
    }
    #pragma unroll
    for (int o = 16; o; o >>= 1) lsum += __shfl_xor_sync(0xFFFFFFFFu, lsum, o);
    float inv = 1.0f / (lsum + e_cs);

    int smax_tile = (q | 127) >> 2;
    __nv_bfloat16* wrow = g_Ws + (long long)warp * (3*NS);
    #pragma unroll
    for (int i = 0; i < 16; i++) {
        int s = lane + i*32;
        if (s > smax_tile) continue;
        float w;
        if (s < slot)       w = v[i] * inv;
        else if (s == slot) w = e_cs * inv;
        else                w = 0.0f;
        __nv_bfloat16 h, l; split2(w, h, l);
        wrow[3*s]     = h;
        wrow[3*s + 1] = h;
        wrow[3*s + 2] = l;
    }
    if (lane == 0) g_wcurr[warp] = e_cs * inv;
}

// --- fixup + output phase (4-wide); writes O split into g_XsO --------------
__global__ void fixup_kernel() {
    int tid = threadIdx.x;                     // 64 threads: 4 queries x 16 d4
    int bhq = blockIdx.x * 4 + (tid >> 4);
    int d   = (tid & 15) << 2;
    int bh = bhq >> 11;
    int q  = bhq & (SEQ - 1);
    int slot = q >> 2, step = q & 3;

    float4 o4 = *(const float4*)&g_Ohead[(long long)bhq * HD + d];
    long long vrow = (long long)(bh*SEQ + slot*KF) * HD + d;
    float pv[4] = {0.f, 0.f, 0.f, 0.f};
    for (int j = 0; j <= step; j++) {
        float4 vj = *(const float4*)&g_Vs[vrow + j*HD];
        pv[0] += vj.x; pv[1] += vj.y; pv[2] += vj.z; pv[3] += vj.w;
    }
    float4 fv = *(const float4*)&g_fullV[((long long)bh*NS + slot) * HD + d];
    float wc = g_wcurr[bhq];

    float ov[4] = {o4.x, o4.y, o4.z, o4.w};
    float fvv[4] = {fv.x, fv.y, fv.z, fv.w};
    float val[4];
    #pragma unroll
    for (int j = 0; j < 4; j++)
        val[j] = (ov[j] + wc * (pv[j] - fvv[j])) * hsign(step, d + j) * 2.0f;

    int b = bh >> 4, h = bh & 15;
    int t = b*SEQ + q;
    int c = h*HD + d;
    uint2 H, L; split4(val, H, L);
    long long base = (long long)t * O_LD;
    *(uint2*)&g_XsO[base + c]        = H;
    *(uint2*)&g_XsO[base + 1024 + c] = H;
    *(uint2*)&g_XsO[base + 2048 + c] = L;
}

// --------------------------------- launcher --------------------------------
extern "C" void kernel_launch(void* const* d_in, const int* in_sizes, int n_in,
                              void* d_out, int out_size)
{
    (void)in_sizes; (void)n_in; (void)out_size;
    const float* X  = (const float*)d_in[0];
    const float* Wq = (const float*)d_in[1];
    const float* Wk = (const float*)d_in[2];
    const float* Wv = (const float*)d_in[3];
    const float* Wo = (const float*)d_in[4];
    const float* Aq = (const float*)d_in[5];
    const float* Bq = (const float*)d_in[6];
    const float* Av = (const float*)d_in[7];
    const float* Bv = (const float*)d_in[8];
    const float* Ao = (const float*)d_in[9];
    const float* Bo = (const float*)d_in[10];
    float* Y = (float*)d_out;

    float *pQKV, *pXA, *pSc, *pOh;
    __nv_bfloat16 *pXsQ, *pXsO, *pWqkv2, *pWoB, *pAB, *pABo, *pQas, *pKTs, *pFVs, *pWw;
    cudaGetSymbolAddress((void**)&pQKV,  g_QKV);
    cudaGetSymbolAddress((void**)&pXA,   g_XA);
    cudaGetSymbolAddress((void**)&pSc,   g_scores);
    cudaGetSymbolAddress((void**)&pOh,   g_Ohead);
    cudaGetSymbolAddress((void**)&pXsQ,  g_XsQ);
    cudaGetSymbolAddress((void**)&pXsO,  g_XsO);
    cudaGetSymbolAddress((void**)&pWqkv2, g_Wqkv2);
    cudaGetSymbolAddress((void**)&pWoB,  g_WoB);
    cudaGetSymbolAddress((void**)&pAB,   g_AB);
    cudaGetSymbolAddress((void**)&pABo,  g_ABo);
    cudaGetSymbolAddress((void**)&pQas,  g_Qas);
    cudaGetSymbolAddress((void**)&pKTs,  g_KTs);
    cudaGetSymbolAddress((void**)&pFVs,  g_FVs);
    cudaGetSymbolAddress((void**)&pWw,   g_Ws);

    const int SM_BIG = 2*(128*(64+8) + 64*(128+8))*2;   // 71680 B <128,128,64,2,4,2>
    const int SM_PV  = 2*(128*(32+8) + 32*(64+8))*2;    // 29696 B <128,64,32,4,2,2>
    cudaFuncSetAttribute(mma_gemm<128,128,64,2,4,2>,
                         cudaFuncAttributeMaxDynamicSharedMemorySize, SM_BIG);
    cudaFuncSetAttribute(mma_gemm<128,64,32,4,2,2>,
                         cudaFuncAttributeMaxDynamicSharedMemorySize, SM_PV);

    const int SPLIT_T = 256;
    #define GRID1D(n) (((n) + SPLIT_T - 1) / SPLIT_T)

    // 1) all input-only splits + rope table, one launch (vectorized)
    mega_prep<<<GRID1D(MEGA_TOTAL), SPLIT_T>>>(X, Wq, Wk, Wv, Wo, Aq, Bq, Av, Bv, Ao, Bo);

    // 2) LoRA stage-1 (q|v, N=128), K=3072 over g_XsQ
    {
        dim3 grid(1, NTOK/128);
        mma_gemm<128,128,64,2,4,2><<<grid, 256, SM_BIG>>>(
            pXsQ, pAB, pXA, NTOK, 128, 3*HID, QK_LD, 128, 128,
            0,0,0, 0, 0);
    }
    // 3) XA split appended into g_XsQ cols 3072..3455
    split_xa_qkv<<<GRID1D(NTOK*16), SPLIT_T>>>(pXA);
    // 4) combined QKV + LoRA projection, K=3456
    {
        dim3 grid(3*HID/128, NTOK/128);   // 24 x 32
        mma_gemm<128,128,64,2,4,2><<<grid, 256, SM_BIG>>>(
            pXsQ, pWqkv2, pQKV, NTOK, 3*HID, QK_LD, QK_LD, 3*HID, 3*HID,
            0,0,0, 0, 0);
    }

    // 5-6) RoPE + phase (4-wide, emits Qa split), slot reduction
    rope_phase_kernel<<<GRID1D(NTOK*HID/4), SPLIT_T>>>();
    reduce_full_kernel<<<GRID1D(NBH*NS*HD), SPLIT_T>>>();

    // 7) scores = Qa @ fullKT (batched, causal tile-skip)
    {
        dim3 grid(NS/128, SEQ/128, NBH);
        mma_gemm<128,128,64,2,4,2><<<grid, 256, SM_BIG>>>(
            pQas, pKTs, pSc, SEQ, NS, 3*HD, 3*HD, NS, NS,
            (long long)SEQ*3*HD, (long long)3*HD*NS, (long long)SEQ*NS,
            0, /*causal=*/1);
    }
    // 8) softmax with current-slot override (register-resident)
    softmax_kernel<<<(NBH*SEQ*32)/256, 256>>>();

    // 9) Ohead = W @ fullV (batched, interleaved causal K-limit)
    {
        dim3 grid(1, SEQ/128, NBH);
        mma_gemm<128,64,32,4,2,2><<<grid, 256, SM_PV>>>(
            pWw, pFVs, pOh, SEQ, HD, 3*NS, 3*NS, HD, HD,
            (long long)SEQ*3*NS, (long long)3*NS*HD, (long long)SEQ*HD,
            0, /*causal=*/2);
    }
    // 10) fixup (4-wide) writes O activations in hhl split into g_XsO
    fixup_kernel<<<NBH*SEQ/4, 64>>>();

    // 11) LoRA-O stage-1 (N=64), K=3072 over g_XsO
    {
        dim3 grid(1, NTOK/128);
        mma_gemm<128,64,32,4,2,2><<<grid, 256, SM_PV>>>(
            pXsO, pABo, pXA, NTOK, LR, 3*HID, O_LD, LR, LR,
            0,0,0, 0, 0);
    }
    // 12) XAo split appended into g_XsO cols 3072..3263
    split_xa_o<<<GRID1D(NTOK*8), SPLIT_T>>>(pXA);
    // 13) combined O + LoRA projection, K=3264 -> Y
    {
        dim3 grid(HID/128, NTOK/128);
        mma_gemm<128,128,64,2,4,2><<<grid, 256, SM_BIG>>>(
            pXsO, pWoB, Y, NTOK, HID, O_LD, O_LD, HID, HID,
            0,0,0, 0, 0);
    }
    #undef GRID1D
}